// round 2
// baseline (speedup 1.0000x reference)
#include <cuda_runtime.h>
#include <math.h>

// Problem dims
#define CB  8
#define CS  1300
#define CD  1080
#define CH  12
#define CDK 90
#define CDP 96              // padded per-head dim (16B-aligned rows)
#define CFF 3240
#define CBS (CB*CS)         // 10400 rows

// ---------------- scratch (static device globals; no runtime alloc) --------
__device__ float g_x2 [(size_t)CBS*CD];   // LN output (reused for LN2)
__device__ float g_q  [(size_t)CBS*CD];
__device__ float g_k  [(size_t)CBS*CD];
__device__ float g_v  [(size_t)CBS*CD];
__device__ float g_qh [(size_t)CB*CH*CS*CDP];  // padded per-head, roped
__device__ float g_kh [(size_t)CB*CH*CS*CDP];
__device__ float g_vh [(size_t)CB*CH*CS*CDP];
__device__ float g_attn[(size_t)CBS*CD];
__device__ float g_res[(size_t)CBS*CD];   // residual after attention
__device__ float g_h1 [(size_t)CBS*CFF];  // FFN intermediate (in-place swiglu)
__device__ float g_sc [(size_t)CB*CH*CS*CS]; // scores / probs (in-place softmax)

// ---------------- generic tiled SGEMM ----------------
// C[M,N] = A[M,K] * op(B)  (op = B or B^T), batched with (outer,inner) strides.
// BM=BN=128, BK=8, 256 threads, 8x8 per-thread micro-tile.
enum { EPI_NONE=0, EPI_SCALE=1, EPI_BIAS=2, EPI_BIAS_RES=3, EPI_SWIGLU=4 };

__device__ __forceinline__ float4 ld4_guard(const float* __restrict__ p,
                                            int r, int rMax, int c, int cMax, int ld)
{
    float4 v = make_float4(0.f, 0.f, 0.f, 0.f);
    if (r < rMax) {
        const float* q = p + (long)r * ld + c;
        if (c + 3 < cMax) {
            v = *reinterpret_cast<const float4*>(q);
        } else {
            if (c     < cMax) v.x = q[0];
            if (c + 1 < cMax) v.y = q[1];
            if (c + 2 < cMax) v.z = q[2];
            if (c + 3 < cMax) v.w = q[3];
        }
    }
    return v;
}

template<int EPI, bool TRANSB, bool CAUSAL, bool TRIK>
__global__ __launch_bounds__(256)
void gemm_k(const float* __restrict__ A, int lda, long aOut, long aIn,
            const float* __restrict__ Bm, int ldb, long bOut, long bIn,
            float* __restrict__ C, int ldc, long cOut, long cIn,
            const float* __restrict__ bias,
            const float* __restrict__ aux, int ldx,
            int M, int N, int K, int innerCnt, float scale)
{
    const int z  = blockIdx.z;
    const int zo = z / innerCnt, zi = z % innerCnt;
    A  += zo * aOut + zi * aIn;
    Bm += zo * bOut + zi * bIn;
    C  += zo * cOut + zi * cIn;

    const int m0 = blockIdx.y * 128;
    const int n0 = blockIdx.x * 128;
    if (CAUSAL && n0 > m0 + 127) return;          // fully-masked tile
    const int kEnd = TRIK ? min(K, m0 + 128) : K; // causal K truncation (P is 0 beyond)

    __shared__ __align__(16) float As[8][128];
    __shared__ __align__(16) float Bs[8][128];

    const int tid = threadIdx.x;
    const int tx = tid & 15;        // 0..15 -> n micro-tile
    const int ty = tid >> 4;        // 0..15 -> m micro-tile

    // load indices
    const int aRow = tid >> 1;            // 0..127
    const int aCol = (tid & 1) * 4;       // 0 or 4
    int bRow, bCol;
    if (!TRANSB) { bRow = tid >> 5;  bCol = (tid & 31) * 4; }  // 8 x 128
    else         { bRow = tid >> 1;  bCol = (tid & 1) * 4;  }  // 128 x 8

    float acc[8][8];
    #pragma unroll
    for (int i = 0; i < 8; i++)
        #pragma unroll
        for (int j = 0; j < 8; j++) acc[i][j] = 0.f;

    for (int k0 = 0; k0 < kEnd; k0 += 8) {
        // --- A tile (128 rows x 8 k), stored transposed As[k][m]
        {
            float4 v = ld4_guard(A, m0 + aRow, M, k0 + aCol, K, lda);
            As[aCol + 0][aRow] = v.x;
            As[aCol + 1][aRow] = v.y;
            As[aCol + 2][aRow] = v.z;
            As[aCol + 3][aRow] = v.w;
        }
        // --- B tile -> Bs[k][n]
        if (!TRANSB) {
            float4 v = ld4_guard(Bm, k0 + bRow, K, n0 + bCol, N, ldb);
            *reinterpret_cast<float4*>(&Bs[bRow][bCol]) = v;
        } else {
            float4 v = ld4_guard(Bm, n0 + bRow, N, k0 + bCol, K, ldb);
            Bs[bCol + 0][bRow] = v.x;
            Bs[bCol + 1][bRow] = v.y;
            Bs[bCol + 2][bRow] = v.z;
            Bs[bCol + 3][bRow] = v.w;
        }
        __syncthreads();

        #pragma unroll
        for (int kk = 0; kk < 8; kk++) {
            float a[8], b[8];
            *reinterpret_cast<float4*>(&a[0]) = *reinterpret_cast<const float4*>(&As[kk][ty*8]);
            *reinterpret_cast<float4*>(&a[4]) = *reinterpret_cast<const float4*>(&As[kk][ty*8+4]);
            *reinterpret_cast<float4*>(&b[0]) = *reinterpret_cast<const float4*>(&Bs[kk][tx*8]);
            *reinterpret_cast<float4*>(&b[4]) = *reinterpret_cast<const float4*>(&Bs[kk][tx*8+4]);
            #pragma unroll
            for (int i = 0; i < 8; i++)
                #pragma unroll
                for (int j = 0; j < 8; j++)
                    acc[i][j] = fmaf(a[i], b[j], acc[i][j]);
        }
        __syncthreads();
    }

    // --- epilogue
    #pragma unroll
    for (int i = 0; i < 8; i++) {
        const int r = m0 + ty * 8 + i;
        if (r >= M) continue;
        #pragma unroll
        for (int j = 0; j < 8; j++) {
            const int c = n0 + tx * 8 + j;
            if (c >= N) continue;
            float v = acc[i][j];
            if (EPI == EPI_SCALE)    v *= scale;
            if (EPI == EPI_BIAS)     v += bias[c];
            if (EPI == EPI_BIAS_RES) v += bias[c] + aux[(long)r * ldx + c];
            if (EPI == EPI_SWIGLU) {
                float h = aux[(long)r * ldx + c];          // x2@W1+b1
                float sg = h / (1.f + __expf(-h));         // silu
                v = sg * (v + bias[c]);                    // * (x2@W3+b3)
            }
            C[(long)r * ldc + c] = v;
        }
    }
}

// ---------------- layernorm (one block per row of 1080) ----------------
__global__ __launch_bounds__(256)
void ln_k(const float* __restrict__ x, const float* __restrict__ g,
          const float* __restrict__ b, float* __restrict__ y)
{
    const long row = blockIdx.x;
    const float* xr = x + row * CD;
    float* yr = y + row * CD;

    float s = 0.f, s2 = 0.f;
    for (int i = threadIdx.x; i < CD; i += 256) {
        float v = xr[i]; s += v; s2 += v * v;
    }
    __shared__ float rs[8], rs2[8];
    __shared__ float bm, br;
    #pragma unroll
    for (int o = 16; o; o >>= 1) {
        s  += __shfl_xor_sync(0xffffffffu, s,  o);
        s2 += __shfl_xor_sync(0xffffffffu, s2, o);
    }
    if ((threadIdx.x & 31) == 0) { rs[threadIdx.x >> 5] = s; rs2[threadIdx.x >> 5] = s2; }
    __syncthreads();
    if (threadIdx.x < 8) {
        float a = rs[threadIdx.x], a2 = rs2[threadIdx.x];
        #pragma unroll
        for (int o = 4; o; o >>= 1) {
            a  += __shfl_xor_sync(0xffu, a,  o);
            a2 += __shfl_xor_sync(0xffu, a2, o);
        }
        if (threadIdx.x == 0) {
            float mean = a / CD;
            float var  = a2 / CD - mean * mean;
            bm = mean;
            br = rsqrtf(var + 1e-5f);
        }
    }
    __syncthreads();
    const float mean = bm, rstd = br;
    for (int i = threadIdx.x; i < CD; i += 256)
        yr[i] = (xr[i] - mean) * rstd * g[i] + b[i];
}

// -------- RoPE + repack into padded per-head layout [B*H, S, 96] ----------
// q,k get RoPE; v is copied. Pad lanes [90,96) are zeroed so GEMMs can run K=96.
__global__ __launch_bounds__(256)
void rope_repack_k(const float* __restrict__ q, const float* __restrict__ k,
                   const float* __restrict__ v,
                   const float* __restrict__ ct, const float* __restrict__ st,
                   float* __restrict__ qh, float* __restrict__ kh,
                   float* __restrict__ vh)
{
    const long total = (long)CB * CH * CS * 48;
    long idx = (long)blockIdx.x * 256 + threadIdx.x;
    if (idx >= total) return;
    const int d = (int)(idx % 48);  idx /= 48;
    const int s = (int)(idx % CS);  idx /= CS;
    const int h = (int)(idx % CH);
    const int b = (int)(idx / CH);

    const long src = ((long)b * CS + s) * CD + h * CDK;
    const long dst = (((long)b * CH + h) * CS + s) * CDP;

    if (d < 45) {
        const float c1 = ct[s * CDK + d],      s1 = st[s * CDK + d];
        const float c2 = ct[s * CDK + d + 45], s2 = st[s * CDK + d + 45];
        float q1 = q[src + d], q2 = q[src + d + 45];
        qh[dst + d]      = q1 * c1 - q2 * s1;
        qh[dst + d + 45] = q2 * c2 + q1 * s2;
        float k1 = k[src + d], k2 = k[src + d + 45];
        kh[dst + d]      = k1 * c1 - k2 * s1;
        kh[dst + d + 45] = k2 * c2 + k1 * s2;
        vh[dst + d]      = v[src + d];
        vh[dst + d + 45] = v[src + d + 45];
    } else {
        const int p = 90 + 2 * (d - 45);   // 90..95
        qh[dst + p] = 0.f; qh[dst + p + 1] = 0.f;
        kh[dst + p] = 0.f; kh[dst + p + 1] = 0.f;
        vh[dst + p] = 0.f; vh[dst + p + 1] = 0.f;
    }
}

// ---------------- causal row softmax (in place), zero-pad to 128-tile ----
__global__ __launch_bounds__(256)
void softmax_k(float* __restrict__ P)
{
    const long row = blockIdx.x;            // over B*H*S rows
    const int s = (int)(row % CS);
    float* pr = P + row * (long)CS;
    const int len = s + 1;

    __shared__ float red[8];
    __shared__ float bmax, bsum;

    float mx = -3.4e38f;
    for (int j = threadIdx.x; j < len; j += 256) mx = fmaxf(mx, pr[j]);
    #pragma unroll
    for (int o = 16; o; o >>= 1) mx = fmaxf(mx, __shfl_xor_sync(0xffffffffu, mx, o));
    if ((threadIdx.x & 31) == 0) red[threadIdx.x >> 5] = mx;
    __syncthreads();
    if (threadIdx.x < 8) {
        float v = red[threadIdx.x];
        #pragma unroll
        for (int o = 4; o; o >>= 1) v = fmaxf(v, __shfl_xor_sync(0xffu, v, o));
        if (threadIdx.x == 0) bmax = v;
    }
    __syncthreads();
    const float m = bmax;

    float sum = 0.f;
    for (int j = threadIdx.x; j < len; j += 256) {
        float e = __expf(pr[j] - m);
        pr[j] = e;
        sum += e;
    }
    __syncthreads();                 // red[] reuse hazard guard
    #pragma unroll
    for (int o = 16; o; o >>= 1) sum += __shfl_xor_sync(0xffffffffu, sum, o);
    if ((threadIdx.x & 31) == 0) red[threadIdx.x >> 5] = sum;
    __syncthreads();
    if (threadIdx.x < 8) {
        float v = red[threadIdx.x];
        #pragma unroll
        for (int o = 4; o; o >>= 1) v += __shfl_xor_sync(0xffu, v, o);
        if (threadIdx.x == 0) bsum = v;
    }
    __syncthreads();
    const float inv = 1.f / bsum;
    for (int j = threadIdx.x; j < len; j += 256) pr[j] *= inv;

    // zero the band (s, tile_end) so the P*V gemm (K truncated to m-tile bound)
    // reads exact zeros above the diagonal
    const int zend = min(CS, ((s >> 7) + 1) << 7);
    for (int j = len + threadIdx.x; j < zend; j += 256) pr[j] = 0.f;
}

// ---------------- host launch ----------------
extern "C" void kernel_launch(void* const* d_in, const int* in_sizes, int n_in,
                              void* d_out, int out_size)
{
    const float* x    = (const float*)d_in[0];
    // d_in[1] = mask (int32) — causal structure is exploited directly
    const float* Wq   = (const float*)d_in[2];
    const float* bq   = (const float*)d_in[3];
    const float* Wk   = (const float*)d_in[4];
    const float* bk   = (const float*)d_in[5];
    const float* Wv   = (const float*)d_in[6];
    const float* bv   = (const float*)d_in[7];
    const float* Wo   = (const float*)d_in[8];
    const float* bo   = (const float*)d_in[9];
    const float* W1   = (const float*)d_in[10];
    const float* b1   = (const float*)d_in[11];
    const float* W2   = (const float*)d_in[12];
    const float* b2   = (const float*)d_in[13];
    const float* W3   = (const float*)d_in[14];
    const float* b3   = (const float*)d_in[15];
    const float* ln1g = (const float*)d_in[16];
    const float* ln1b = (const float*)d_in[17];
    const float* ln2g = (const float*)d_in[18];
    const float* ln2b = (const float*)d_in[19];
    const float* rc   = (const float*)d_in[20];
    const float* rs   = (const float*)d_in[21];
    float* out = (float*)d_out;

    float *x2, *q, *k, *v, *qh, *kh, *vh, *attn, *res, *h1, *sc;
    cudaGetSymbolAddress((void**)&x2,   g_x2);
    cudaGetSymbolAddress((void**)&q,    g_q);
    cudaGetSymbolAddress((void**)&k,    g_k);
    cudaGetSymbolAddress((void**)&v,    g_v);
    cudaGetSymbolAddress((void**)&qh,   g_qh);
    cudaGetSymbolAddress((void**)&kh,   g_kh);
    cudaGetSymbolAddress((void**)&vh,   g_vh);
    cudaGetSymbolAddress((void**)&attn, g_attn);
    cudaGetSymbolAddress((void**)&res,  g_res);
    cudaGetSymbolAddress((void**)&h1,   g_h1);
    cudaGetSymbolAddress((void**)&sc,   g_sc);

    const float iscale = 1.f / sqrtf((float)CDK);

    // 1) LN1
    ln_k<<<CBS, 256>>>(x, ln1g, ln1b, x2);

    // 2) Q,K,V projections (bias fused)
    dim3 gD((CD + 127) / 128, (CBS + 127) / 128, 1);
    gemm_k<EPI_BIAS, false, false, false><<<gD, 256>>>(
        x2, CD, 0, 0, Wq, CD, 0, 0, q, CD, 0, 0, bq, nullptr, 0, CBS, CD, CD, 1, 1.f);
    gemm_k<EPI_BIAS, false, false, false><<<gD, 256>>>(
        x2, CD, 0, 0, Wk, CD, 0, 0, k, CD, 0, 0, bk, nullptr, 0, CBS, CD, CD, 1, 1.f);
    gemm_k<EPI_BIAS, false, false, false><<<gD, 256>>>(
        x2, CD, 0, 0, Wv, CD, 0, 0, v, CD, 0, 0, bv, nullptr, 0, CBS, CD, CD, 1, 1.f);

    // 3) RoPE + repack to padded per-head layout
    {
        long total = (long)CB * CH * CS * 48;
        rope_repack_k<<<(unsigned)((total + 255) / 256), 256>>>(q, k, v, rc, rs, qh, kh, vh);
    }

    // 4) scores = q k^T / sqrt(dk), batched over (b,h), upper tiles skipped
    {
        dim3 g((CS + 127) / 128, (CS + 127) / 128, CB * CH);
        gemm_k<EPI_SCALE, true, true, false><<<g, 256>>>(
            qh, CDP, (long)CS * CDP, 0,
            kh, CDP, (long)CS * CDP, 0,
            sc, CS, (long)CS * CS, 0,
            nullptr, nullptr, 0, CS, CS, CDP, 1, iscale);
    }

    // 5) causal softmax (in place)
    softmax_k<<<CB * CH * CS, 256>>>(sc);

    // 6) attn = P @ V, K-loop truncated at the causal tile bound,
    //    output scattered back to interleaved [B,S,H*DK]
    {
        dim3 g(1, (CS + 127) / 128, CB * CH);
        gemm_k<EPI_NONE, false, false, true><<<g, 256>>>(
            sc, CS, (long)CH * CS * CS, (long)CS * CS,
            vh, CDP, (long)CH * CS * CDP, (long)CS * CDP,
            attn, CD, (long)CS * CD, CDK,
            nullptr, nullptr, 0, CS, CDK, CS, CH, 1.f);
    }

    // 7) O-projection + bias + residual(x)
    gemm_k<EPI_BIAS_RES, false, false, false><<<gD, 256>>>(
        attn, CD, 0, 0, Wo, CD, 0, 0, res, CD, 0, 0, bo, x, CD, CBS, CD, CD, 1, 1.f);

    // 8) LN2
    ln_k<<<CBS, 256>>>(res, ln2g, ln2b, x2);

    // 9) h1 = x2@W1 + b1
    dim3 gF((CFF + 127) / 128, (CBS + 127) / 128, 1);
    gemm_k<EPI_BIAS, false, false, false><<<gF, 256>>>(
        x2, CD, 0, 0, W1, CFF, 0, 0, h1, CFF, 0, 0, b1, nullptr, 0, CBS, CFF, CD, 1, 1.f);

    // 10) h1 = silu(h1) * (x2@W3 + b3)   (in-place swiglu epilogue)
    gemm_k<EPI_SWIGLU, false, false, false><<<gF, 256>>>(
        x2, CD, 0, 0, W3, CFF, 0, 0, h1, CFF, 0, 0, b3, h1, CFF, CBS, CFF, CD, 1, 1.f);

    // 11) out = res + h1@W2 + b2
    gemm_k<EPI_BIAS_RES, false, false, false><<<gD, 256>>>(
        h1, CFF, 0, 0, W2, CD, 0, 0, out, CD, 0, 0, b2, res, CD, CBS, CD, CFF, 1, 1.f);
}

// round 3
// speedup vs baseline: 1.2512x; 1.2512x over previous
#include <cuda_runtime.h>
#include <mma.h>
#include <math.h>

using namespace nvcuda;

// Problem dims
#define CB  8
#define CS  1300
#define CD  1080
#define CH  12
#define CDK 90
#define CDP 96              // padded per-head dim (16B-aligned rows)
#define CFF 3240
#define CBS (CB*CS)         // 10400 rows

// ---------------- scratch (static device globals; no runtime alloc) --------
__device__ float g_x2 [(size_t)CBS*CD];   // LN output (reused for LN2)
__device__ float g_q  [(size_t)CBS*CD];
__device__ float g_k  [(size_t)CBS*CD];
__device__ float g_v  [(size_t)CBS*CD];
__device__ float g_qh [(size_t)CB*CH*CS*CDP];  // padded per-head, roped
__device__ float g_kh [(size_t)CB*CH*CS*CDP];
__device__ float g_vh [(size_t)CB*CH*CS*CDP];
__device__ float g_attn[(size_t)CBS*CD];
__device__ float g_res[(size_t)CBS*CD];   // residual after attention
__device__ float g_h1 [(size_t)CBS*CFF];  // FFN intermediate (in-place swiglu)
__device__ float g_sc [(size_t)CB*CH*CS*CS]; // scores / probs (in-place softmax)

enum { EPI_NONE=0, EPI_SCALE=1, EPI_BIAS=2, EPI_BIAS_RES=3, EPI_SWIGLU=4 };

__device__ __forceinline__ float4 ld4_guard(const float* __restrict__ p,
                                            int r, int rMax, int c, int cMax, int ld)
{
    float4 v = make_float4(0.f, 0.f, 0.f, 0.f);
    if (r < rMax) {
        const float* q = p + (long)r * ld + c;
        if (c + 3 < cMax) {
            v = *reinterpret_cast<const float4*>(q);
        } else {
            if (c     < cMax) v.x = q[0];
            if (c + 1 < cMax) v.y = q[1];
            if (c + 2 < cMax) v.z = q[2];
            if (c + 3 < cMax) v.w = q[3];
        }
    }
    return v;
}

// ---------------- TF32 tensor-core GEMM ----------------
// C[M,N] = A[M,K] * op(B) (+ epilogue).  op = B ([K,N]) or B^T (B stored [N,K]).
// Block tile 128x128, BK=16, 256 threads = 8 warps (4 along M x 2 along N),
// warp tile 32x64 = 2x4 wmma m16n16k8 fragments.
#define ALD 24              // As row stride (floats), 96B (32B-aligned rows)
#define BLD 136             // Bs row stride for [K][N] layout
#define CLD 24              // epilogue stage row stride

template<int EPI, bool TRANSB, bool CAUSAL, bool TRIK>
__global__ __launch_bounds__(256)
void gemm_tc(const float* __restrict__ A, int lda, long aOut, long aIn,
             const float* __restrict__ Bm, int ldb, long bOut, long bIn,
             float* __restrict__ C, int ldc, long cOut, long cIn,
             const float* __restrict__ bias,
             const float* __restrict__ aux, int ldx,
             int M, int N, int K, int innerCnt, float scale)
{
    const int z  = blockIdx.z;
    const int zo = z / innerCnt, zi = z % innerCnt;
    A  += zo * aOut + zi * aIn;
    Bm += zo * bOut + zi * bIn;
    C  += zo * cOut + zi * cIn;

    const int m0 = blockIdx.y * 128;
    const int n0 = blockIdx.x * 128;
    if (CAUSAL && n0 > m0 + 127) return;          // fully-masked tile
    const int kEnd = TRIK ? min(K, m0 + 128) : K; // causal K truncation (P is 0 beyond)

    __shared__ __align__(32) float As[128 * ALD];   // [m][k] padded
    __shared__ __align__(32) float Bs[128 * ALD];   // trans: [n][k]x24 ; notrans: [k][n]x136 (16*136<128*24)
    __shared__ __align__(32) float Cs[8 * 16 * CLD]; // per-warp epilogue stage

    const int tid = threadIdx.x;
    const int wid = tid >> 5;
    const int lane = tid & 31;
    const int warp_m = wid & 3;          // 0..3 -> m offset *32
    const int warp_n = wid >> 2;         // 0..1 -> n offset *64

    wmma::fragment<wmma::accumulator, 16, 16, 8, float> acc[2][4];
    #pragma unroll
    for (int i = 0; i < 2; i++)
        #pragma unroll
        for (int j = 0; j < 4; j++) wmma::fill_fragment(acc[i][j], 0.f);

    // global-load indices
    const int aRow = tid >> 1;            // 0..127
    const int aC0  = (tid & 1) * 8;       // 0 or 8
    const int bRowT = tid >> 1;           // TRANSB: n-row 0..127
    const int bC0T  = (tid & 1) * 8;
    const int bRowN = tid >> 4;           // !TRANSB: k-row 0..15
    const int bC0N  = (tid & 15) * 8;

    for (int k0 = 0; k0 < kEnd; k0 += 16) {
        // A tile: [128][16]
        {
            float4 v0 = ld4_guard(A, m0 + aRow, M, k0 + aC0,     K, lda);
            float4 v1 = ld4_guard(A, m0 + aRow, M, k0 + aC0 + 4, K, lda);
            *reinterpret_cast<float4*>(&As[aRow * ALD + aC0])     = v0;
            *reinterpret_cast<float4*>(&As[aRow * ALD + aC0 + 4]) = v1;
        }
        // B tile
        if (TRANSB) {   // B stored [N,K]; keep [n][k] layout, col_major frags
            float4 v0 = ld4_guard(Bm, n0 + bRowT, N, k0 + bC0T,     K, ldb);
            float4 v1 = ld4_guard(Bm, n0 + bRowT, N, k0 + bC0T + 4, K, ldb);
            *reinterpret_cast<float4*>(&Bs[bRowT * ALD + bC0T])     = v0;
            *reinterpret_cast<float4*>(&Bs[bRowT * ALD + bC0T + 4]) = v1;
        } else {        // B stored [K,N]; [k][n] layout, row_major frags
            float4 v0 = ld4_guard(Bm, k0 + bRowN, K, n0 + bC0N,     N, ldb);
            float4 v1 = ld4_guard(Bm, k0 + bRowN, K, n0 + bC0N + 4, N, ldb);
            *reinterpret_cast<float4*>(&Bs[bRowN * BLD + bC0N])     = v0;
            *reinterpret_cast<float4*>(&Bs[bRowN * BLD + bC0N + 4]) = v1;
        }
        __syncthreads();

        #pragma unroll
        for (int kk = 0; kk < 16; kk += 8) {
            wmma::fragment<wmma::matrix_a, 16, 16, 8, wmma::precision::tf32, wmma::row_major> af[2];
            #pragma unroll
            for (int i = 0; i < 2; i++) {
                wmma::load_matrix_sync(af[i], &As[(warp_m * 32 + i * 16) * ALD + kk], ALD);
                #pragma unroll
                for (int t = 0; t < af[i].num_elements; t++)
                    af[i].x[t] = wmma::__float_to_tf32(af[i].x[t]);
            }
            if (TRANSB) {
                #pragma unroll
                for (int j = 0; j < 4; j++) {
                    wmma::fragment<wmma::matrix_b, 16, 16, 8, wmma::precision::tf32, wmma::col_major> bf;
                    wmma::load_matrix_sync(bf, &Bs[(warp_n * 64 + j * 16) * ALD + kk], ALD);
                    #pragma unroll
                    for (int t = 0; t < bf.num_elements; t++)
                        bf.x[t] = wmma::__float_to_tf32(bf.x[t]);
                    wmma::mma_sync(acc[0][j], af[0], bf, acc[0][j]);
                    wmma::mma_sync(acc[1][j], af[1], bf, acc[1][j]);
                }
            } else {
                #pragma unroll
                for (int j = 0; j < 4; j++) {
                    wmma::fragment<wmma::matrix_b, 16, 16, 8, wmma::precision::tf32, wmma::row_major> bf;
                    wmma::load_matrix_sync(bf, &Bs[kk * BLD + warp_n * 64 + j * 16], BLD);
                    #pragma unroll
                    for (int t = 0; t < bf.num_elements; t++)
                        bf.x[t] = wmma::__float_to_tf32(bf.x[t]);
                    wmma::mma_sync(acc[0][j], af[0], bf, acc[0][j]);
                    wmma::mma_sync(acc[1][j], af[1], bf, acc[1][j]);
                }
            }
        }
        __syncthreads();
    }

    // ---- epilogue: stage each 16x16 fragment through smem, guarded stores ----
    float* stage = &Cs[wid * 16 * CLD];
    const int er  = lane >> 1;           // 0..15
    const int ec0 = (lane & 1) * 8;      // 0 or 8
    #pragma unroll
    for (int i = 0; i < 2; i++) {
        #pragma unroll
        for (int j = 0; j < 4; j++) {
            wmma::store_matrix_sync(stage, acc[i][j], CLD, wmma::mem_row_major);
            __syncwarp();
            const int gr = m0 + warp_m * 32 + i * 16 + er;
            const int gcb = n0 + warp_n * 64 + j * 16 + ec0;
            if (gr < M) {
                #pragma unroll
                for (int u = 0; u < 8; u++) {
                    const int gc = gcb + u;
                    if (gc >= N) break;
                    float v = stage[er * CLD + ec0 + u];
                    if (EPI == EPI_SCALE)    v *= scale;
                    if (EPI == EPI_BIAS)     v += bias[gc];
                    if (EPI == EPI_BIAS_RES) v += bias[gc] + aux[(long)gr * ldx + gc];
                    if (EPI == EPI_SWIGLU) {
                        float h = aux[(long)gr * ldx + gc];      // x2@W1+b1
                        float sg = h / (1.f + __expf(-h));       // silu
                        v = sg * (v + bias[gc]);                 // * (x2@W3+b3)
                    }
                    C[(long)gr * ldc + gc] = v;
                }
            }
            __syncwarp();
        }
    }
}

// ---------------- layernorm (one block per row of 1080) ----------------
__global__ __launch_bounds__(256)
void ln_k(const float* __restrict__ x, const float* __restrict__ g,
          const float* __restrict__ b, float* __restrict__ y)
{
    const long row = blockIdx.x;
    const float* xr = x + row * CD;
    float* yr = y + row * CD;

    float s = 0.f, s2 = 0.f;
    for (int i = threadIdx.x; i < CD; i += 256) {
        float v = xr[i]; s += v; s2 += v * v;
    }
    __shared__ float rs[8], rs2[8];
    __shared__ float bm, br;
    #pragma unroll
    for (int o = 16; o; o >>= 1) {
        s  += __shfl_xor_sync(0xffffffffu, s,  o);
        s2 += __shfl_xor_sync(0xffffffffu, s2, o);
    }
    if ((threadIdx.x & 31) == 0) { rs[threadIdx.x >> 5] = s; rs2[threadIdx.x >> 5] = s2; }
    __syncthreads();
    if (threadIdx.x < 8) {
        float a = rs[threadIdx.x], a2 = rs2[threadIdx.x];
        #pragma unroll
        for (int o = 4; o; o >>= 1) {
            a  += __shfl_xor_sync(0xffu, a,  o);
            a2 += __shfl_xor_sync(0xffu, a2, o);
        }
        if (threadIdx.x == 0) {
            float mean = a / CD;
            float var  = a2 / CD - mean * mean;
            bm = mean;
            br = rsqrtf(var + 1e-5f);
        }
    }
    __syncthreads();
    const float mean = bm, rstd = br;
    for (int i = threadIdx.x; i < CD; i += 256)
        yr[i] = (xr[i] - mean) * rstd * g[i] + b[i];
}

// -------- RoPE + repack into padded per-head layout [B*H, S, 96] ----------
__global__ __launch_bounds__(256)
void rope_repack_k(const float* __restrict__ q, const float* __restrict__ k,
                   const float* __restrict__ v,
                   const float* __restrict__ ct, const float* __restrict__ st,
                   float* __restrict__ qh, float* __restrict__ kh,
                   float* __restrict__ vh)
{
    const long total = (long)CB * CH * CS * 48;
    long idx = (long)blockIdx.x * 256 + threadIdx.x;
    if (idx >= total) return;
    const int d = (int)(idx % 48);  idx /= 48;
    const int s = (int)(idx % CS);  idx /= CS;
    const int h = (int)(idx % CH);
    const int b = (int)(idx / CH);

    const long src = ((long)b * CS + s) * CD + h * CDK;
    const long dst = (((long)b * CH + h) * CS + s) * CDP;

    if (d < 45) {
        const float c1 = ct[s * CDK + d],      s1 = st[s * CDK + d];
        const float c2 = ct[s * CDK + d + 45], s2 = st[s * CDK + d + 45];
        float q1 = q[src + d], q2 = q[src + d + 45];
        qh[dst + d]      = q1 * c1 - q2 * s1;
        qh[dst + d + 45] = q2 * c2 + q1 * s2;
        float k1 = k[src + d], k2 = k[src + d + 45];
        kh[dst + d]      = k1 * c1 - k2 * s1;
        kh[dst + d + 45] = k2 * c2 + k1 * s2;
        vh[dst + d]      = v[src + d];
        vh[dst + d + 45] = v[src + d + 45];
    } else {
        const int p = 90 + 2 * (d - 45);   // 90..95
        qh[dst + p] = 0.f; qh[dst + p + 1] = 0.f;
        kh[dst + p] = 0.f; kh[dst + p + 1] = 0.f;
        vh[dst + p] = 0.f; vh[dst + p + 1] = 0.f;
    }
}

// ---------------- causal row softmax (in place), zero-pad to 128-tile ----
__global__ __launch_bounds__(256)
void softmax_k(float* __restrict__ P)
{
    const long row = blockIdx.x;            // over B*H*S rows
    const int s = (int)(row % CS);
    float* pr = P + row * (long)CS;
    const int len = s + 1;

    __shared__ float red[8];
    __shared__ float bmax, bsum;

    float mx = -3.4e38f;
    for (int j = threadIdx.x; j < len; j += 256) mx = fmaxf(mx, pr[j]);
    #pragma unroll
    for (int o = 16; o; o >>= 1) mx = fmaxf(mx, __shfl_xor_sync(0xffffffffu, mx, o));
    if ((threadIdx.x & 31) == 0) red[threadIdx.x >> 5] = mx;
    __syncthreads();
    if (threadIdx.x < 8) {
        float v = red[threadIdx.x];
        #pragma unroll
        for (int o = 4; o; o >>= 1) v = fmaxf(v, __shfl_xor_sync(0xffu, v, o));
        if (threadIdx.x == 0) bmax = v;
    }
    __syncthreads();
    const float m = bmax;

    float sum = 0.f;
    for (int j = threadIdx.x; j < len; j += 256) {
        float e = __expf(pr[j] - m);
        pr[j] = e;
        sum += e;
    }
    __syncthreads();
    #pragma unroll
    for (int o = 16; o; o >>= 1) sum += __shfl_xor_sync(0xffffffffu, sum, o);
    if ((threadIdx.x & 31) == 0) red[threadIdx.x >> 5] = sum;
    __syncthreads();
    if (threadIdx.x < 8) {
        float v = red[threadIdx.x];
        #pragma unroll
        for (int o = 4; o; o >>= 1) v += __shfl_xor_sync(0xffu, v, o);
        if (threadIdx.x == 0) bsum = v;
    }
    __syncthreads();
    const float inv = 1.f / bsum;
    for (int j = threadIdx.x; j < len; j += 256) pr[j] *= inv;

    const int zend = min(CS, ((s >> 7) + 1) << 7);
    for (int j = len + threadIdx.x; j < zend; j += 256) pr[j] = 0.f;
}

// ---------------- host launch ----------------
extern "C" void kernel_launch(void* const* d_in, const int* in_sizes, int n_in,
                              void* d_out, int out_size)
{
    const float* x    = (const float*)d_in[0];
    const float* Wq   = (const float*)d_in[2];
    const float* bq   = (const float*)d_in[3];
    const float* Wk   = (const float*)d_in[4];
    const float* bk   = (const float*)d_in[5];
    const float* Wv   = (const float*)d_in[6];
    const float* bv   = (const float*)d_in[7];
    const float* Wo   = (const float*)d_in[8];
    const float* bo   = (const float*)d_in[9];
    const float* W1   = (const float*)d_in[10];
    const float* b1   = (const float*)d_in[11];
    const float* W2   = (const float*)d_in[12];
    const float* b2   = (const float*)d_in[13];
    const float* W3   = (const float*)d_in[14];
    const float* b3   = (const float*)d_in[15];
    const float* ln1g = (const float*)d_in[16];
    const float* ln1b = (const float*)d_in[17];
    const float* ln2g = (const float*)d_in[18];
    const float* ln2b = (const float*)d_in[19];
    const float* rc   = (const float*)d_in[20];
    const float* rs   = (const float*)d_in[21];
    float* out = (float*)d_out;

    float *x2, *q, *k, *v, *qh, *kh, *vh, *attn, *res, *h1, *sc;
    cudaGetSymbolAddress((void**)&x2,   g_x2);
    cudaGetSymbolAddress((void**)&q,    g_q);
    cudaGetSymbolAddress((void**)&k,    g_k);
    cudaGetSymbolAddress((void**)&v,    g_v);
    cudaGetSymbolAddress((void**)&qh,   g_qh);
    cudaGetSymbolAddress((void**)&kh,   g_kh);
    cudaGetSymbolAddress((void**)&vh,   g_vh);
    cudaGetSymbolAddress((void**)&attn, g_attn);
    cudaGetSymbolAddress((void**)&res,  g_res);
    cudaGetSymbolAddress((void**)&h1,   g_h1);
    cudaGetSymbolAddress((void**)&sc,   g_sc);

    const float iscale = 1.f / sqrtf((float)CDK);

    // 1) LN1
    ln_k<<<CBS, 256>>>(x, ln1g, ln1b, x2);

    // 2) Q,K,V projections (bias fused)
    dim3 gD((CD + 127) / 128, (CBS + 127) / 128, 1);
    gemm_tc<EPI_BIAS, false, false, false><<<gD, 256>>>(
        x2, CD, 0, 0, Wq, CD, 0, 0, q, CD, 0, 0, bq, nullptr, 0, CBS, CD, CD, 1, 1.f);
    gemm_tc<EPI_BIAS, false, false, false><<<gD, 256>>>(
        x2, CD, 0, 0, Wk, CD, 0, 0, k, CD, 0, 0, bk, nullptr, 0, CBS, CD, CD, 1, 1.f);
    gemm_tc<EPI_BIAS, false, false, false><<<gD, 256>>>(
        x2, CD, 0, 0, Wv, CD, 0, 0, v, CD, 0, 0, bv, nullptr, 0, CBS, CD, CD, 1, 1.f);

    // 3) RoPE + repack to padded per-head layout
    {
        long total = (long)CB * CH * CS * 48;
        rope_repack_k<<<(unsigned)((total + 255) / 256), 256>>>(q, k, v, rc, rs, qh, kh, vh);
    }

    // 4) scores = q k^T / sqrt(dk), batched over (b,h), upper tiles skipped
    {
        dim3 g((CS + 127) / 128, (CS + 127) / 128, CB * CH);
        gemm_tc<EPI_SCALE, true, true, false><<<g, 256>>>(
            qh, CDP, (long)CS * CDP, 0,
            kh, CDP, (long)CS * CDP, 0,
            sc, CS, (long)CS * CS, 0,
            nullptr, nullptr, 0, CS, CS, CDP, 1, iscale);
    }

    // 5) causal softmax (in place)
    softmax_k<<<CB * CH * CS, 256>>>(sc);

    // 6) attn = P @ V, K-loop truncated at the causal tile bound,
    //    output scattered back to interleaved [B,S,H*DK]
    {
        dim3 g(1, (CS + 127) / 128, CB * CH);
        gemm_tc<EPI_NONE, false, false, true><<<g, 256>>>(
            sc, CS, (long)CH * CS * CS, (long)CS * CS,
            vh, CDP, (long)CH * CS * CDP, (long)CS * CDP,
            attn, CD, (long)CS * CD, CDK,
            nullptr, nullptr, 0, CS, CDK, CS, CH, 1.f);
    }

    // 7) O-projection + bias + residual(x)
    gemm_tc<EPI_BIAS_RES, false, false, false><<<gD, 256>>>(
        attn, CD, 0, 0, Wo, CD, 0, 0, res, CD, 0, 0, bo, x, CD, CBS, CD, CD, 1, 1.f);

    // 8) LN2
    ln_k<<<CBS, 256>>>(res, ln2g, ln2b, x2);

    // 9) h1 = x2@W1 + b1
    dim3 gF((CFF + 127) / 128, (CBS + 127) / 128, 1);
    gemm_tc<EPI_BIAS, false, false, false><<<gF, 256>>>(
        x2, CD, 0, 0, W1, CFF, 0, 0, h1, CFF, 0, 0, b1, nullptr, 0, CBS, CFF, CD, 1, 1.f);

    // 10) h1 = silu(h1) * (x2@W3 + b3)   (in-place swiglu epilogue)
    gemm_tc<EPI_SWIGLU, false, false, false><<<gF, 256>>>(
        x2, CD, 0, 0, W3, CFF, 0, 0, h1, CFF, 0, 0, b3, h1, CFF, CBS, CFF, CD, 1, 1.f);

    // 11) out = res + h1@W2 + b2
    gemm_tc<EPI_BIAS_RES, false, false, false><<<gD, 256>>>(
        h1, CFF, 0, 0, W2, CD, 0, 0, out, CD, 0, 0, b2, res, CD, CBS, CD, CFF, 1, 1.f);
}

// round 4
// speedup vs baseline: 1.7236x; 1.3776x over previous
#include <cuda_runtime.h>
#include <mma.h>
#include <math.h>

using namespace nvcuda;

// Problem dims
#define CB  8
#define CS  1300
#define CD  1080
#define CH  12
#define CDK 90
#define CDP 96              // padded per-head dim (16B-aligned rows)
#define CFF 3240
#define CBS (CB*CS)         // 10400 rows

// ---------------- scratch (static device globals; no runtime alloc) --------
__device__ float g_x2 [(size_t)CBS*CD];
__device__ float g_q  [(size_t)CBS*CD];
__device__ float g_k  [(size_t)CBS*CD];
__device__ float g_v  [(size_t)CBS*CD];
__device__ float g_qh [(size_t)CB*CH*CS*CDP];
__device__ float g_kh [(size_t)CB*CH*CS*CDP];
__device__ float g_vh [(size_t)CB*CH*CS*CDP];
__device__ float g_attn[(size_t)CBS*CD];
__device__ float g_res[(size_t)CBS*CD];
__device__ float g_h1 [(size_t)CBS*CFF];
__device__ float g_sc [(size_t)CB*CH*CS*CS];

enum { EPI_NONE=0, EPI_SCALE=1, EPI_BIAS=2, EPI_BIAS_RES=3, EPI_SWIGLU=4 };

// 16B async copy with zero-fill predicate
__device__ __forceinline__ void cp_async16(float* smem, const float* gmem, bool pred)
{
    unsigned saddr = (unsigned)__cvta_generic_to_shared(smem);
    int sz = pred ? 16 : 0;
    asm volatile("cp.async.cg.shared.global [%0], [%1], 16, %2;\n"
                 :: "r"(saddr), "l"(gmem), "r"(sz));
}
__device__ __forceinline__ void cp_commit() { asm volatile("cp.async.commit_group;\n"); }
__device__ __forceinline__ void cp_wait_all() { asm volatile("cp.async.wait_group 0;\n"); }

// ---------------- TF32 tensor-core GEMM, 2-stage cp.async pipeline --------
// Block tile 128x128, BK=16, 256 threads = 8 warps (4 M x 2 N),
// warp tile 32x64 = 2x4 wmma m16n16k8 fragments.
#define ALD 24              // As row stride (floats)
#define BLD 136             // Bs row stride for [K][N] layout
#define CLD 24              // epilogue stage row stride

template<int EPI, bool TRANSB, bool CAUSAL, bool TRIK>
__global__ __launch_bounds__(256, 2)
void gemm_tc(const float* __restrict__ A, int lda, long aOut, long aIn,
             const float* __restrict__ Bm, int ldb, long bOut, long bIn,
             float* __restrict__ C, int ldc, long cOut, long cIn,
             const float* __restrict__ bias,
             const float* __restrict__ aux, int ldx,
             int M, int N, int K, int innerCnt, float scale)
{
    const int z  = blockIdx.z;
    const int zo = z / innerCnt, zi = z % innerCnt;
    A  += zo * aOut + zi * aIn;
    Bm += zo * bOut + zi * bIn;
    C  += zo * cOut + zi * cIn;

    const int m0 = blockIdx.y * 128;
    const int n0 = blockIdx.x * 128;
    if (CAUSAL && n0 > m0 + 127) return;
    const int kEnd  = TRIK ? min(K, m0 + 128) : K;
    const int nIter = (kEnd + 15) >> 4;

    __shared__ __align__(16) float As[2][128 * ALD];
    __shared__ __align__(16) float Bs[2][128 * ALD];   // notrans uses 16*BLD <= 128*ALD

    const int tid = threadIdx.x;
    const int wid = tid >> 5;
    const int lane = tid & 31;
    const int warp_m = wid & 3;
    const int warp_n = wid >> 2;

    // load coords
    const int aRow = tid >> 1;            // 0..127
    const int aC0  = (tid & 1) * 8;       // 0 or 8
    const int bRowT = tid >> 1;
    const int bC0T  = (tid & 1) * 8;
    const int bRowN = tid >> 4;           // 0..15
    const int bC0N  = (tid & 15) * 8;

    const bool aRowOk = (m0 + aRow) < M;
    const bool bRowOkT = TRANSB && ((n0 + bRowT) < N);
    const float* aBase = A + (long)(m0 + aRow) * lda + aC0;
    const float* bBaseT = Bm + (long)(n0 + bRowT) * ldb + bC0T;
    const float* bBaseN = Bm + (long)bRowN * ldb + n0 + bC0N;
    const bool bColOkN = (n0 + bC0N) < N;         // chunks 4-aligned; N rows readable
    const bool bColOkN4 = (n0 + bC0N + 4) < N;

    wmma::fragment<wmma::accumulator, 16, 16, 8, float> acc[2][4];
    #pragma unroll
    for (int i = 0; i < 2; i++)
        #pragma unroll
        for (int j = 0; j < 4; j++) wmma::fill_fragment(acc[i][j], 0.f);

    // ---- issue loads for chunk it into buffer buf
    auto issue = [&](int it, int buf) {
        const int k0 = it << 4;
        // A tile [128][16]
        cp_async16(&As[buf][aRow * ALD + aC0],     aBase + k0,     aRowOk && (k0 + aC0     < kEnd));
        cp_async16(&As[buf][aRow * ALD + aC0 + 4], aBase + k0 + 4, aRowOk && (k0 + aC0 + 4 < kEnd));
        if (TRANSB) {
            cp_async16(&Bs[buf][bRowT * ALD + bC0T],     bBaseT + k0,     bRowOkT && (k0 + bC0T     < kEnd));
            cp_async16(&Bs[buf][bRowT * ALD + bC0T + 4], bBaseT + k0 + 4, bRowOkT && (k0 + bC0T + 4 < kEnd));
        } else {
            const bool rOk = (k0 + bRowN) < kEnd;
            cp_async16(&Bs[buf][bRowN * BLD + bC0N],     bBaseN + (long)k0 * ldb,     rOk && bColOkN);
            cp_async16(&Bs[buf][bRowN * BLD + bC0N + 4], bBaseN + (long)k0 * ldb + 4, rOk && bColOkN4);
        }
    };

    issue(0, 0);
    cp_commit();

    for (int it = 0; it < nIter; it++) {
        const int buf = it & 1;
        cp_wait_all();
        __syncthreads();
        if (it + 1 < nIter) { issue(it + 1, buf ^ 1); cp_commit(); }

        #pragma unroll
        for (int kk = 0; kk < 16; kk += 8) {
            wmma::fragment<wmma::matrix_a, 16, 16, 8, wmma::precision::tf32, wmma::row_major> af[2];
            #pragma unroll
            for (int i = 0; i < 2; i++) {
                wmma::load_matrix_sync(af[i], &As[buf][(warp_m * 32 + i * 16) * ALD + kk], ALD);
                #pragma unroll
                for (int t = 0; t < af[i].num_elements; t++)
                    af[i].x[t] = wmma::__float_to_tf32(af[i].x[t]);
            }
            if (TRANSB) {
                #pragma unroll
                for (int j = 0; j < 4; j++) {
                    wmma::fragment<wmma::matrix_b, 16, 16, 8, wmma::precision::tf32, wmma::col_major> bf;
                    wmma::load_matrix_sync(bf, &Bs[buf][(warp_n * 64 + j * 16) * ALD + kk], ALD);
                    #pragma unroll
                    for (int t = 0; t < bf.num_elements; t++)
                        bf.x[t] = wmma::__float_to_tf32(bf.x[t]);
                    wmma::mma_sync(acc[0][j], af[0], bf, acc[0][j]);
                    wmma::mma_sync(acc[1][j], af[1], bf, acc[1][j]);
                }
            } else {
                #pragma unroll
                for (int j = 0; j < 4; j++) {
                    wmma::fragment<wmma::matrix_b, 16, 16, 8, wmma::precision::tf32, wmma::row_major> bf;
                    wmma::load_matrix_sync(bf, &Bs[buf][kk * BLD + warp_n * 64 + j * 16], BLD);
                    #pragma unroll
                    for (int t = 0; t < bf.num_elements; t++)
                        bf.x[t] = wmma::__float_to_tf32(bf.x[t]);
                    wmma::mma_sync(acc[0][j], af[0], bf, acc[0][j]);
                    wmma::mma_sync(acc[1][j], af[1], bf, acc[1][j]);
                }
            }
        }
        __syncthreads();
    }

    // ---- epilogue: stage fragments through smem (reuse As[0]), guarded stores
    float* stage = &As[0][wid * 16 * CLD];
    const int er  = lane >> 1;
    const int ec0 = (lane & 1) * 8;
    #pragma unroll
    for (int i = 0; i < 2; i++) {
        #pragma unroll
        for (int j = 0; j < 4; j++) {
            wmma::store_matrix_sync(stage, acc[i][j], CLD, wmma::mem_row_major);
            __syncwarp();
            const int gr = m0 + warp_m * 32 + i * 16 + er;
            const int gcb = n0 + warp_n * 64 + j * 16 + ec0;
            if (gr < M) {
                #pragma unroll
                for (int u = 0; u < 8; u++) {
                    const int gc = gcb + u;
                    if (gc >= N) break;
                    float v = stage[er * CLD + ec0 + u];
                    if (EPI == EPI_SCALE)    v *= scale;
                    if (EPI == EPI_BIAS)     v += bias[gc];
                    if (EPI == EPI_BIAS_RES) v += bias[gc] + aux[(long)gr * ldx + gc];
                    if (EPI == EPI_SWIGLU) {
                        float h = aux[(long)gr * ldx + gc];
                        float sg = h / (1.f + __expf(-h));
                        v = sg * (v + bias[gc]);
                    }
                    C[(long)gr * ldc + gc] = v;
                }
            }
            __syncwarp();
        }
    }
}

// ---------------- layernorm ----------------
__global__ __launch_bounds__(256)
void ln_k(const float* __restrict__ x, const float* __restrict__ g,
          const float* __restrict__ b, float* __restrict__ y)
{
    const long row = blockIdx.x;
    const float* xr = x + row * CD;
    float* yr = y + row * CD;

    float s = 0.f, s2 = 0.f;
    for (int i = threadIdx.x; i < CD; i += 256) {
        float v = xr[i]; s += v; s2 += v * v;
    }
    __shared__ float rs[8], rs2[8];
    __shared__ float bm, br;
    #pragma unroll
    for (int o = 16; o; o >>= 1) {
        s  += __shfl_xor_sync(0xffffffffu, s,  o);
        s2 += __shfl_xor_sync(0xffffffffu, s2, o);
    }
    if ((threadIdx.x & 31) == 0) { rs[threadIdx.x >> 5] = s; rs2[threadIdx.x >> 5] = s2; }
    __syncthreads();
    if (threadIdx.x < 8) {
        float a = rs[threadIdx.x], a2 = rs2[threadIdx.x];
        #pragma unroll
        for (int o = 4; o; o >>= 1) {
            a  += __shfl_xor_sync(0xffu, a,  o);
            a2 += __shfl_xor_sync(0xffu, a2, o);
        }
        if (threadIdx.x == 0) {
            float mean = a / CD;
            float var  = a2 / CD - mean * mean;
            bm = mean;
            br = rsqrtf(var + 1e-5f);
        }
    }
    __syncthreads();
    const float mean = bm, rstd = br;
    for (int i = threadIdx.x; i < CD; i += 256)
        yr[i] = (xr[i] - mean) * rstd * g[i] + b[i];
}

// -------- RoPE + repack into padded per-head layout [B*H, S, 96] ----------
__global__ __launch_bounds__(256)
void rope_repack_k(const float* __restrict__ q, const float* __restrict__ k,
                   const float* __restrict__ v,
                   const float* __restrict__ ct, const float* __restrict__ st,
                   float* __restrict__ qh, float* __restrict__ kh,
                   float* __restrict__ vh)
{
    const long total = (long)CB * CH * CS * 48;
    long idx = (long)blockIdx.x * 256 + threadIdx.x;
    if (idx >= total) return;
    const int d = (int)(idx % 48);  idx /= 48;
    const int s = (int)(idx % CS);  idx /= CS;
    const int h = (int)(idx % CH);
    const int b = (int)(idx / CH);

    const long src = ((long)b * CS + s) * CD + h * CDK;
    const long dst = (((long)b * CH + h) * CS + s) * CDP;

    if (d < 45) {
        const float c1 = ct[s * CDK + d],      s1 = st[s * CDK + d];
        const float c2 = ct[s * CDK + d + 45], s2 = st[s * CDK + d + 45];
        float q1 = q[src + d], q2 = q[src + d + 45];
        qh[dst + d]      = q1 * c1 - q2 * s1;
        qh[dst + d + 45] = q2 * c2 + q1 * s2;
        float k1 = k[src + d], k2 = k[src + d + 45];
        kh[dst + d]      = k1 * c1 - k2 * s1;
        kh[dst + d + 45] = k2 * c2 + k1 * s2;
        vh[dst + d]      = v[src + d];
        vh[dst + d + 45] = v[src + d + 45];
    } else {
        const int p = 90 + 2 * (d - 45);
        qh[dst + p] = 0.f; qh[dst + p + 1] = 0.f;
        kh[dst + p] = 0.f; kh[dst + p + 1] = 0.f;
        vh[dst + p] = 0.f; vh[dst + p + 1] = 0.f;
    }
}

// ---------------- causal row softmax (in place) ----------------
__global__ __launch_bounds__(256)
void softmax_k(float* __restrict__ P)
{
    const long row = blockIdx.x;
    const int s = (int)(row % CS);
    float* pr = P + row * (long)CS;
    const int len = s + 1;

    __shared__ float red[8];
    __shared__ float bmax, bsum;

    float mx = -3.4e38f;
    for (int j = threadIdx.x; j < len; j += 256) mx = fmaxf(mx, pr[j]);
    #pragma unroll
    for (int o = 16; o; o >>= 1) mx = fmaxf(mx, __shfl_xor_sync(0xffffffffu, mx, o));
    if ((threadIdx.x & 31) == 0) red[threadIdx.x >> 5] = mx;
    __syncthreads();
    if (threadIdx.x < 8) {
        float v = red[threadIdx.x];
        #pragma unroll
        for (int o = 4; o; o >>= 1) v = fmaxf(v, __shfl_xor_sync(0xffu, v, o));
        if (threadIdx.x == 0) bmax = v;
    }
    __syncthreads();
    const float m = bmax;

    float sum = 0.f;
    for (int j = threadIdx.x; j < len; j += 256) {
        float e = __expf(pr[j] - m);
        pr[j] = e;
        sum += e;
    }
    __syncthreads();
    #pragma unroll
    for (int o = 16; o; o >>= 1) sum += __shfl_xor_sync(0xffffffffu, sum, o);
    if ((threadIdx.x & 31) == 0) red[threadIdx.x >> 5] = sum;
    __syncthreads();
    if (threadIdx.x < 8) {
        float v = red[threadIdx.x];
        #pragma unroll
        for (int o = 4; o; o >>= 1) v += __shfl_xor_sync(0xffu, v, o);
        if (threadIdx.x == 0) bsum = v;
    }
    __syncthreads();
    const float inv = 1.f / bsum;
    for (int j = threadIdx.x; j < len; j += 256) pr[j] *= inv;

    const int zend = min(CS, ((s >> 7) + 1) << 7);
    for (int j = len + threadIdx.x; j < zend; j += 256) pr[j] = 0.f;
}

// ---------------- host launch ----------------
extern "C" void kernel_launch(void* const* d_in, const int* in_sizes, int n_in,
                              void* d_out, int out_size)
{
    const float* x    = (const float*)d_in[0];
    const float* Wq   = (const float*)d_in[2];
    const float* bq   = (const float*)d_in[3];
    const float* Wk   = (const float*)d_in[4];
    const float* bk   = (const float*)d_in[5];
    const float* Wv   = (const float*)d_in[6];
    const float* bv   = (const float*)d_in[7];
    const float* Wo   = (const float*)d_in[8];
    const float* bo   = (const float*)d_in[9];
    const float* W1   = (const float*)d_in[10];
    const float* b1   = (const float*)d_in[11];
    const float* W2   = (const float*)d_in[12];
    const float* b2   = (const float*)d_in[13];
    const float* W3   = (const float*)d_in[14];
    const float* b3   = (const float*)d_in[15];
    const float* ln1g = (const float*)d_in[16];
    const float* ln1b = (const float*)d_in[17];
    const float* ln2g = (const float*)d_in[18];
    const float* ln2b = (const float*)d_in[19];
    const float* rc   = (const float*)d_in[20];
    const float* rs   = (const float*)d_in[21];
    float* out = (float*)d_out;

    float *x2, *q, *k, *v, *qh, *kh, *vh, *attn, *res, *h1, *sc;
    cudaGetSymbolAddress((void**)&x2,   g_x2);
    cudaGetSymbolAddress((void**)&q,    g_q);
    cudaGetSymbolAddress((void**)&k,    g_k);
    cudaGetSymbolAddress((void**)&v,    g_v);
    cudaGetSymbolAddress((void**)&qh,   g_qh);
    cudaGetSymbolAddress((void**)&kh,   g_kh);
    cudaGetSymbolAddress((void**)&vh,   g_vh);
    cudaGetSymbolAddress((void**)&attn, g_attn);
    cudaGetSymbolAddress((void**)&res,  g_res);
    cudaGetSymbolAddress((void**)&h1,   g_h1);
    cudaGetSymbolAddress((void**)&sc,   g_sc);

    const float iscale = 1.f / sqrtf((float)CDK);

    // 1) LN1
    ln_k<<<CBS, 256>>>(x, ln1g, ln1b, x2);

    // 2) Q,K,V projections (bias fused)
    dim3 gD((CD + 127) / 128, (CBS + 127) / 128, 1);
    gemm_tc<EPI_BIAS, false, false, false><<<gD, 256>>>(
        x2, CD, 0, 0, Wq, CD, 0, 0, q, CD, 0, 0, bq, nullptr, 0, CBS, CD, CD, 1, 1.f);
    gemm_tc<EPI_BIAS, false, false, false><<<gD, 256>>>(
        x2, CD, 0, 0, Wk, CD, 0, 0, k, CD, 0, 0, bk, nullptr, 0, CBS, CD, CD, 1, 1.f);
    gemm_tc<EPI_BIAS, false, false, false><<<gD, 256>>>(
        x2, CD, 0, 0, Wv, CD, 0, 0, v, CD, 0, 0, bv, nullptr, 0, CBS, CD, CD, 1, 1.f);

    // 3) RoPE + repack to padded per-head layout
    {
        long total = (long)CB * CH * CS * 48;
        rope_repack_k<<<(unsigned)((total + 255) / 256), 256>>>(q, k, v, rc, rs, qh, kh, vh);
    }

    // 4) scores = q k^T / sqrt(dk)
    {
        dim3 g((CS + 127) / 128, (CS + 127) / 128, CB * CH);
        gemm_tc<EPI_SCALE, true, true, false><<<g, 256>>>(
            qh, CDP, (long)CS * CDP, 0,
            kh, CDP, (long)CS * CDP, 0,
            sc, CS, (long)CS * CS, 0,
            nullptr, nullptr, 0, CS, CS, CDP, 1, iscale);
    }

    // 5) causal softmax (in place)
    softmax_k<<<CB * CH * CS, 256>>>(sc);

    // 6) attn = P @ V (K truncated at causal tile bound)
    {
        dim3 g(1, (CS + 127) / 128, CB * CH);
        gemm_tc<EPI_NONE, false, false, true><<<g, 256>>>(
            sc, CS, (long)CH * CS * CS, (long)CS * CS,
            vh, CDP, (long)CH * CS * CDP, (long)CS * CDP,
            attn, CD, (long)CS * CD, CDK,
            nullptr, nullptr, 0, CS, CDK, CS, CH, 1.f);
    }

    // 7) O-projection + bias + residual(x)
    gemm_tc<EPI_BIAS_RES, false, false, false><<<gD, 256>>>(
        attn, CD, 0, 0, Wo, CD, 0, 0, res, CD, 0, 0, bo, x, CD, CBS, CD, CD, 1, 1.f);

    // 8) LN2
    ln_k<<<CBS, 256>>>(res, ln2g, ln2b, x2);

    // 9) h1 = x2@W1 + b1
    dim3 gF((CFF + 127) / 128, (CBS + 127) / 128, 1);
    gemm_tc<EPI_BIAS, false, false, false><<<gF, 256>>>(
        x2, CD, 0, 0, W1, CFF, 0, 0, h1, CFF, 0, 0, b1, nullptr, 0, CBS, CFF, CD, 1, 1.f);

    // 10) h1 = silu(h1) * (x2@W3 + b3)
    gemm_tc<EPI_SWIGLU, false, false, false><<<gF, 256>>>(
        x2, CD, 0, 0, W3, CFF, 0, 0, h1, CFF, 0, 0, b3, h1, CFF, CBS, CFF, CD, 1, 1.f);

    // 11) out = res + h1@W2 + b2
    gemm_tc<EPI_BIAS_RES, false, false, false><<<gD, 256>>>(
        h1, CFF, 0, 0, W2, CD, 0, 0, out, CD, 0, 0, b2, res, CD, CBS, CD, CFF, 1, 1.f);
}

// round 5
// speedup vs baseline: 1.8342x; 1.0642x over previous
#include <cuda_runtime.h>
#include <mma.h>
#include <math.h>

using namespace nvcuda;

// Problem dims
#define CB  8
#define CS  1300
#define CD  1080
#define CH  12
#define CDK 90
#define CDP 96              // padded per-head dim
#define CFF 3240
#define CBS (CB*CS)         // 10400 rows

// ---------------- scratch (static device globals) --------
__device__ float g_x2 [(size_t)CBS*CD];
__device__ float g_qh [(size_t)CB*CH*CS*CDP];
__device__ float g_kh [(size_t)CB*CH*CS*CDP];
__device__ float g_vh [(size_t)CB*CH*CS*CDP];
__device__ float g_attn[(size_t)CBS*CD];
__device__ float g_res[(size_t)CBS*CD];
__device__ float g_h1 [(size_t)CBS*CFF];   // QKV output, later FFN intermediate
__device__ float g_sc [(size_t)CB*CH*CS*CS];
__device__ float g_wqkv[(size_t)CD*CFF];   // packed [1080][3240] Wq|Wk|Wv
__device__ float g_bqkv[CFF];

enum { EPI_NONE=0, EPI_SCALE=1, EPI_BIAS=2, EPI_BIAS_RES=3, EPI_SWIGLU=4 };

__device__ __forceinline__ void cp_async16(float* smem, const float* gmem, bool pred)
{
    unsigned saddr = (unsigned)__cvta_generic_to_shared(smem);
    int sz = pred ? 16 : 0;
    asm volatile("cp.async.cg.shared.global [%0], [%1], 16, %2;\n"
                 :: "r"(saddr), "l"(gmem), "r"(sz));
}
__device__ __forceinline__ void cp_commit() { asm volatile("cp.async.commit_group;\n"); }

// ---------------- TF32 tensor-core GEMM, 3-stage cp.async pipeline --------
// Block tile 128x128, BK=16, 256 threads = 8 warps (4 M x 2 N),
// warp tile 32x64 = 2x4 wmma m16n16k8 fragments. Dynamic smem.
#define ALD 24
#define BLD 136
#define CLD 24
#define STG_F (128*ALD)            // floats per stage per array (3072)
#define SMEM_BYTES (3*STG_F*2*4)   // 73728 B

template<int EPI, bool TRANSB, bool CAUSAL, bool TRIK>
__global__ __launch_bounds__(256, 2)
void gemm_tc(const float* __restrict__ A, int lda, long aOut, long aIn,
             const float* __restrict__ Bm, int ldb, long bOut, long bIn,
             float* __restrict__ C, int ldc, long cOut, long cIn,
             const float* __restrict__ bias,
             const float* __restrict__ aux, int ldx,
             int M, int N, int K, int innerCnt, float scale)
{
    const int z  = blockIdx.z;
    const int zo = z / innerCnt, zi = z % innerCnt;
    A  += zo * aOut + zi * aIn;
    Bm += zo * bOut + zi * bIn;
    C  += zo * cOut + zi * cIn;

    const int m0 = blockIdx.y * 128;
    const int n0 = blockIdx.x * 128;
    if (CAUSAL && n0 > m0 + 127) return;
    const int kEnd  = TRIK ? min(K, m0 + 128) : K;
    const int nIter = (kEnd + 15) >> 4;

    extern __shared__ __align__(16) float smem_dyn[];
    float* As = smem_dyn;               // [3][STG_F]
    float* Bs = smem_dyn + 3 * STG_F;   // [3][STG_F]

    const int tid = threadIdx.x;
    const int wid = tid >> 5;
    const int lane = tid & 31;
    const int warp_m = wid & 3;
    const int warp_n = wid >> 2;

    const int aRow = tid >> 1;
    const int aC0  = (tid & 1) * 8;
    const int bRowT = tid >> 1;
    const int bC0T  = (tid & 1) * 8;
    const int bRowN = tid >> 4;
    const int bC0N  = (tid & 15) * 8;

    const bool aRowOk = (m0 + aRow) < M;
    const bool bRowOkT = TRANSB && ((n0 + bRowT) < N);
    const float* aBase = A + (long)(m0 + aRow) * lda + aC0;
    const float* bBaseT = Bm + (long)(n0 + bRowT) * ldb + bC0T;
    const float* bBaseN = Bm + (long)bRowN * ldb + n0 + bC0N;
    const bool bColOkN = (n0 + bC0N) < N;
    const bool bColOkN4 = (n0 + bC0N + 4) < N;

    wmma::fragment<wmma::accumulator, 16, 16, 8, float> acc[2][4];
    #pragma unroll
    for (int i = 0; i < 2; i++)
        #pragma unroll
        for (int j = 0; j < 4; j++) wmma::fill_fragment(acc[i][j], 0.f);

    auto issue = [&](int it, int buf) {
        const int k0 = it << 4;
        float* as = As + buf * STG_F;
        float* bs = Bs + buf * STG_F;
        cp_async16(&as[aRow * ALD + aC0],     aBase + k0,     aRowOk && (k0 + aC0     < kEnd));
        cp_async16(&as[aRow * ALD + aC0 + 4], aBase + k0 + 4, aRowOk && (k0 + aC0 + 4 < kEnd));
        if (TRANSB) {
            cp_async16(&bs[bRowT * ALD + bC0T],     bBaseT + k0,     bRowOkT && (k0 + bC0T     < kEnd));
            cp_async16(&bs[bRowT * ALD + bC0T + 4], bBaseT + k0 + 4, bRowOkT && (k0 + bC0T + 4 < kEnd));
        } else {
            const bool rOk = (k0 + bRowN) < kEnd;
            cp_async16(&bs[bRowN * BLD + bC0N],     bBaseN + (long)k0 * ldb,     rOk && bColOkN);
            cp_async16(&bs[bRowN * BLD + bC0N + 4], bBaseN + (long)k0 * ldb + 4, rOk && bColOkN4);
        }
    };

    issue(0, 0);
    cp_commit();
    if (nIter > 1) { issue(1, 1); cp_commit(); }

    for (int it = 0; it < nIter; it++) {
        const int buf = it % 3;
        // chunk `it` must be complete; allow the (it+1) prefetch group to stay in flight
        if (it + 1 < nIter) asm volatile("cp.async.wait_group 1;\n");
        else                asm volatile("cp.async.wait_group 0;\n");
        __syncthreads();
        if (it + 2 < nIter) { issue(it + 2, (it + 2) % 3); cp_commit(); }

        const float* as = As + buf * STG_F;
        const float* bs = Bs + buf * STG_F;
        #pragma unroll
        for (int kk = 0; kk < 16; kk += 8) {
            wmma::fragment<wmma::matrix_a, 16, 16, 8, wmma::precision::tf32, wmma::row_major> af[2];
            #pragma unroll
            for (int i = 0; i < 2; i++)
                wmma::load_matrix_sync(af[i], &as[(warp_m * 32 + i * 16) * ALD + kk], ALD);
            if (TRANSB) {
                #pragma unroll
                for (int j = 0; j < 4; j++) {
                    wmma::fragment<wmma::matrix_b, 16, 16, 8, wmma::precision::tf32, wmma::col_major> bf;
                    wmma::load_matrix_sync(bf, &bs[(warp_n * 64 + j * 16) * ALD + kk], ALD);
                    wmma::mma_sync(acc[0][j], af[0], bf, acc[0][j]);
                    wmma::mma_sync(acc[1][j], af[1], bf, acc[1][j]);
                }
            } else {
                #pragma unroll
                for (int j = 0; j < 4; j++) {
                    wmma::fragment<wmma::matrix_b, 16, 16, 8, wmma::precision::tf32, wmma::row_major> bf;
                    wmma::load_matrix_sync(bf, &bs[kk * BLD + warp_n * 64 + j * 16], BLD);
                    wmma::mma_sync(acc[0][j], af[0], bf, acc[0][j]);
                    wmma::mma_sync(acc[1][j], af[1], bf, acc[1][j]);
                }
            }
        }
        __syncthreads();
    }

    // ---- epilogue: stage fragments through smem, guarded stores
    float* stage = &As[wid * 16 * CLD];
    const int er  = lane >> 1;
    const int ec0 = (lane & 1) * 8;
    #pragma unroll
    for (int i = 0; i < 2; i++) {
        #pragma unroll
        for (int j = 0; j < 4; j++) {
            wmma::store_matrix_sync(stage, acc[i][j], CLD, wmma::mem_row_major);
            __syncwarp();
            const int gr = m0 + warp_m * 32 + i * 16 + er;
            const int gcb = n0 + warp_n * 64 + j * 16 + ec0;
            if (gr < M) {
                #pragma unroll
                for (int u = 0; u < 8; u++) {
                    const int gc = gcb + u;
                    if (gc >= N) break;
                    float v = stage[er * CLD + ec0 + u];
                    if (EPI == EPI_SCALE)    v *= scale;
                    if (EPI == EPI_BIAS)     v += bias[gc];
                    if (EPI == EPI_BIAS_RES) v += bias[gc] + aux[(long)gr * ldx + gc];
                    if (EPI == EPI_SWIGLU) {
                        float h = aux[(long)gr * ldx + gc];
                        float sg = h / (1.f + __expf(-h));
                        v = sg * (v + bias[gc]);
                    }
                    C[(long)gr * ldc + gc] = v;
                }
            }
            __syncwarp();
        }
    }
}

// ---------------- pack Wq|Wk|Wv -> [1080][3240], biases -> [3240] ----------
__global__ __launch_bounds__(256)
void pack_qkv_k(const float* __restrict__ Wq, const float* __restrict__ Wk,
                const float* __restrict__ Wv,
                const float* __restrict__ bq, const float* __restrict__ bk,
                const float* __restrict__ bv,
                float* __restrict__ W, float* __restrict__ b)
{
    const int NW4 = CD * (CD / 4);         // 291600 float4 per weight
    long idx = (long)blockIdx.x * 256 + threadIdx.x;
    if (idx < NW4) {
        int r = (int)(idx / (CD / 4));
        int c = (int)(idx % (CD / 4)) * 4;
        float4 vq = *reinterpret_cast<const float4*>(Wq + (long)r * CD + c);
        float4 vk = *reinterpret_cast<const float4*>(Wk + (long)r * CD + c);
        float4 vv = *reinterpret_cast<const float4*>(Wv + (long)r * CD + c);
        *reinterpret_cast<float4*>(W + (long)r * CFF + c)            = vq;
        *reinterpret_cast<float4*>(W + (long)r * CFF + CD + c)       = vk;
        *reinterpret_cast<float4*>(W + (long)r * CFF + 2 * CD + c)   = vv;
    } else if (idx < NW4 + CD / 4) {
        int c = (int)(idx - NW4) * 4;
        *reinterpret_cast<float4*>(b + c)          = *reinterpret_cast<const float4*>(bq + c);
        *reinterpret_cast<float4*>(b + CD + c)     = *reinterpret_cast<const float4*>(bk + c);
        *reinterpret_cast<float4*>(b + 2 * CD + c) = *reinterpret_cast<const float4*>(bv + c);
    }
}

// ---------------- layernorm ----------------
__global__ __launch_bounds__(256)
void ln_k(const float* __restrict__ x, const float* __restrict__ g,
          const float* __restrict__ b, float* __restrict__ y)
{
    const long row = blockIdx.x;
    const float* xr = x + row * CD;
    float* yr = y + row * CD;

    float s = 0.f, s2 = 0.f;
    for (int i = threadIdx.x; i < CD; i += 256) {
        float v = xr[i]; s += v; s2 += v * v;
    }
    __shared__ float rs[8], rs2[8];
    __shared__ float bm, br;
    #pragma unroll
    for (int o = 16; o; o >>= 1) {
        s  += __shfl_xor_sync(0xffffffffu, s,  o);
        s2 += __shfl_xor_sync(0xffffffffu, s2, o);
    }
    if ((threadIdx.x & 31) == 0) { rs[threadIdx.x >> 5] = s; rs2[threadIdx.x >> 5] = s2; }
    __syncthreads();
    if (threadIdx.x < 8) {
        float a = rs[threadIdx.x], a2 = rs2[threadIdx.x];
        #pragma unroll
        for (int o = 4; o; o >>= 1) {
            a  += __shfl_xor_sync(0xffu, a,  o);
            a2 += __shfl_xor_sync(0xffu, a2, o);
        }
        if (threadIdx.x == 0) {
            float mean = a / CD;
            float var  = a2 / CD - mean * mean;
            bm = mean;
            br = rsqrtf(var + 1e-5f);
        }
    }
    __syncthreads();
    const float mean = bm, rstd = br;
    for (int i = threadIdx.x; i < CD; i += 256)
        yr[i] = (xr[i] - mean) * rstd * g[i] + b[i];
}

// -------- RoPE + repack from fused QKV [row][3240] to [B*H, S, 96] ----------
__global__ __launch_bounds__(256)
void rope_repack_k(const float* __restrict__ qkv,
                   const float* __restrict__ ct, const float* __restrict__ st,
                   float* __restrict__ qh, float* __restrict__ kh,
                   float* __restrict__ vh)
{
    const long total = (long)CB * CH * CS * 48;
    long idx = (long)blockIdx.x * 256 + threadIdx.x;
    if (idx >= total) return;
    const int d = (int)(idx % 48);  idx /= 48;
    const int s = (int)(idx % CS);  idx /= CS;
    const int h = (int)(idx % CH);
    const int b = (int)(idx / CH);

    const long src = ((long)b * CS + s) * CFF + h * CDK;
    const long dst = (((long)b * CH + h) * CS + s) * CDP;

    if (d < 45) {
        const float c1 = ct[s * CDK + d],      s1 = st[s * CDK + d];
        const float c2 = ct[s * CDK + d + 45], s2 = st[s * CDK + d + 45];
        float q1 = qkv[src + d],          q2 = qkv[src + d + 45];
        qh[dst + d]      = q1 * c1 - q2 * s1;
        qh[dst + d + 45] = q2 * c2 + q1 * s2;
        float k1 = qkv[src + CD + d],     k2 = qkv[src + CD + d + 45];
        kh[dst + d]      = k1 * c1 - k2 * s1;
        kh[dst + d + 45] = k2 * c2 + k1 * s2;
        vh[dst + d]      = qkv[src + 2 * CD + d];
        vh[dst + d + 45] = qkv[src + 2 * CD + d + 45];
    } else {
        const int p = 90 + 2 * (d - 45);
        qh[dst + p] = 0.f; qh[dst + p + 1] = 0.f;
        kh[dst + p] = 0.f; kh[dst + p + 1] = 0.f;
        vh[dst + p] = 0.f; vh[dst + p + 1] = 0.f;
    }
}

// ---------------- causal row softmax (in place) ----------------
__global__ __launch_bounds__(256)
void softmax_k(float* __restrict__ P)
{
    const long row = blockIdx.x;
    const int s = (int)(row % CS);
    float* pr = P + row * (long)CS;
    const int len = s + 1;

    __shared__ float red[8];
    __shared__ float bmax, bsum;

    float mx = -3.4e38f;
    for (int j = threadIdx.x; j < len; j += 256) mx = fmaxf(mx, pr[j]);
    #pragma unroll
    for (int o = 16; o; o >>= 1) mx = fmaxf(mx, __shfl_xor_sync(0xffffffffu, mx, o));
    if ((threadIdx.x & 31) == 0) red[threadIdx.x >> 5] = mx;
    __syncthreads();
    if (threadIdx.x < 8) {
        float v = red[threadIdx.x];
        #pragma unroll
        for (int o = 4; o; o >>= 1) v = fmaxf(v, __shfl_xor_sync(0xffu, v, o));
        if (threadIdx.x == 0) bmax = v;
    }
    __syncthreads();
    const float m = bmax;

    float sum = 0.f;
    for (int j = threadIdx.x; j < len; j += 256) {
        float e = __expf(pr[j] - m);
        pr[j] = e;
        sum += e;
    }
    __syncthreads();
    #pragma unroll
    for (int o = 16; o; o >>= 1) sum += __shfl_xor_sync(0xffffffffu, sum, o);
    if ((threadIdx.x & 31) == 0) red[threadIdx.x >> 5] = sum;
    __syncthreads();
    if (threadIdx.x < 8) {
        float v = red[threadIdx.x];
        #pragma unroll
        for (int o = 4; o; o >>= 1) v += __shfl_xor_sync(0xffu, v, o);
        if (threadIdx.x == 0) bsum = v;
    }
    __syncthreads();
    const float inv = 1.f / bsum;
    for (int j = threadIdx.x; j < len; j += 256) pr[j] *= inv;

    const int zend = min(CS, ((s >> 7) + 1) << 7);
    for (int j = len + threadIdx.x; j < zend; j += 256) pr[j] = 0.f;
}

// ---------------- host launch ----------------
extern "C" void kernel_launch(void* const* d_in, const int* in_sizes, int n_in,
                              void* d_out, int out_size)
{
    const float* x    = (const float*)d_in[0];
    const float* Wq   = (const float*)d_in[2];
    const float* bq   = (const float*)d_in[3];
    const float* Wk   = (const float*)d_in[4];
    const float* bk   = (const float*)d_in[5];
    const float* Wv   = (const float*)d_in[6];
    const float* bv   = (const float*)d_in[7];
    const float* Wo   = (const float*)d_in[8];
    const float* bo   = (const float*)d_in[9];
    const float* W1   = (const float*)d_in[10];
    const float* b1   = (const float*)d_in[11];
    const float* W2   = (const float*)d_in[12];
    const float* b2   = (const float*)d_in[13];
    const float* W3   = (const float*)d_in[14];
    const float* b3   = (const float*)d_in[15];
    const float* ln1g = (const float*)d_in[16];
    const float* ln1b = (const float*)d_in[17];
    const float* ln2g = (const float*)d_in[18];
    const float* ln2b = (const float*)d_in[19];
    const float* rc   = (const float*)d_in[20];
    const float* rs   = (const float*)d_in[21];
    float* out = (float*)d_out;

    float *x2, *qh, *kh, *vh, *attn, *res, *h1, *sc, *wqkv, *bqkv;
    cudaGetSymbolAddress((void**)&x2,   g_x2);
    cudaGetSymbolAddress((void**)&qh,   g_qh);
    cudaGetSymbolAddress((void**)&kh,   g_kh);
    cudaGetSymbolAddress((void**)&vh,   g_vh);
    cudaGetSymbolAddress((void**)&attn, g_attn);
    cudaGetSymbolAddress((void**)&res,  g_res);
    cudaGetSymbolAddress((void**)&h1,   g_h1);
    cudaGetSymbolAddress((void**)&sc,   g_sc);
    cudaGetSymbolAddress((void**)&wqkv, g_wqkv);
    cudaGetSymbolAddress((void**)&bqkv, g_bqkv);

    // raise dynamic smem cap for all GEMM instantiations (idempotent)
    static bool attrDone = false;
    if (!attrDone) {
        cudaFuncSetAttribute(gemm_tc<EPI_BIAS, false, false, false>,  cudaFuncAttributeMaxDynamicSharedMemorySize, SMEM_BYTES);
        cudaFuncSetAttribute(gemm_tc<EPI_SCALE, true,  true,  false>, cudaFuncAttributeMaxDynamicSharedMemorySize, SMEM_BYTES);
        cudaFuncSetAttribute(gemm_tc<EPI_NONE,  false, false, true>,  cudaFuncAttributeMaxDynamicSharedMemorySize, SMEM_BYTES);
        cudaFuncSetAttribute(gemm_tc<EPI_BIAS_RES, false, false, false>, cudaFuncAttributeMaxDynamicSharedMemorySize, SMEM_BYTES);
        cudaFuncSetAttribute(gemm_tc<EPI_SWIGLU, false, false, false>,   cudaFuncAttributeMaxDynamicSharedMemorySize, SMEM_BYTES);
        attrDone = true;
    }

    const float iscale = 1.f / sqrtf((float)CDK);

    // 0) pack QKV weights+biases
    {
        int total = CD * (CD / 4) + CD / 4;
        pack_qkv_k<<<(total + 255) / 256, 256>>>(Wq, Wk, Wv, bq, bk, bv, wqkv, bqkv);
    }

    // 1) LN1
    ln_k<<<CBS, 256>>>(x, ln1g, ln1b, x2);

    // 2) fused QKV projection (bias fused): h1[r][3240]
    dim3 gQKV((CFF + 127) / 128, (CBS + 127) / 128, 1);
    gemm_tc<EPI_BIAS, false, false, false><<<gQKV, 256, SMEM_BYTES>>>(
        x2, CD, 0, 0, wqkv, CFF, 0, 0, h1, CFF, 0, 0, bqkv, nullptr, 0, CBS, CFF, CD, 1, 1.f);

    // 3) RoPE + repack to padded per-head layout
    {
        long total = (long)CB * CH * CS * 48;
        rope_repack_k<<<(unsigned)((total + 255) / 256), 256>>>(h1, rc, rs, qh, kh, vh);
    }

    // 4) scores = q k^T / sqrt(dk)
    {
        dim3 g((CS + 127) / 128, (CS + 127) / 128, CB * CH);
        gemm_tc<EPI_SCALE, true, true, false><<<g, 256, SMEM_BYTES>>>(
            qh, CDP, (long)CS * CDP, 0,
            kh, CDP, (long)CS * CDP, 0,
            sc, CS, (long)CS * CS, 0,
            nullptr, nullptr, 0, CS, CS, CDP, 1, iscale);
    }

    // 5) causal softmax (in place)
    softmax_k<<<CB * CH * CS, 256>>>(sc);

    // 6) attn = P @ V (K truncated at causal tile bound)
    {
        dim3 g(1, (CS + 127) / 128, CB * CH);
        gemm_tc<EPI_NONE, false, false, true><<<g, 256, SMEM_BYTES>>>(
            sc, CS, (long)CH * CS * CS, (long)CS * CS,
            vh, CDP, (long)CH * CS * CDP, (long)CS * CDP,
            attn, CD, (long)CS * CD, CDK,
            nullptr, nullptr, 0, CS, CDK, CS, CH, 1.f);
    }

    // 7) O-projection + bias + residual(x)
    dim3 gD((CD + 127) / 128, (CBS + 127) / 128, 1);
    gemm_tc<EPI_BIAS_RES, false, false, false><<<gD, 256, SMEM_BYTES>>>(
        attn, CD, 0, 0, Wo, CD, 0, 0, res, CD, 0, 0, bo, x, CD, CBS, CD, CD, 1, 1.f);

    // 8) LN2
    ln_k<<<CBS, 256>>>(res, ln2g, ln2b, x2);

    // 9) h1 = x2@W1 + b1
    dim3 gF((CFF + 127) / 128, (CBS + 127) / 128, 1);
    gemm_tc<EPI_BIAS, false, false, false><<<gF, 256, SMEM_BYTES>>>(
        x2, CD, 0, 0, W1, CFF, 0, 0, h1, CFF, 0, 0, b1, nullptr, 0, CBS, CFF, CD, 1, 1.f);

    // 10) h1 = silu(h1) * (x2@W3 + b3)
    gemm_tc<EPI_SWIGLU, false, false, false><<<gF, 256, SMEM_BYTES>>>(
        x2, CD, 0, 0, W3, CFF, 0, 0, h1, CFF, 0, 0, b3, h1, CFF, CBS, CFF, CD, 1, 1.f);

    // 11) out = res + h1@W2 + b2
    gemm_tc<EPI_BIAS_RES, false, false, false><<<gD, 256, SMEM_BYTES>>>(
        h1, CFF, 0, 0, W2, CD, 0, 0, out, CD, 0, 0, b2, res, CD, CBS, CD, CFF, 1, 1.f);
}

// round 6
// speedup vs baseline: 2.0239x; 1.1034x over previous
#include <cuda_runtime.h>
#include <mma.h>
#include <math.h>

using namespace nvcuda;

// Problem dims
#define CB  8
#define CS  1300
#define CD  1080
#define CH  12
#define CDK 90
#define CDP 96              // padded per-head dim
#define CFF 3240
#define CBS (CB*CS)         // 10400 rows

// ---------------- scratch (static device globals) --------
__device__ float g_x2 [(size_t)CBS*CD];
__device__ float g_qh [(size_t)CB*CH*CS*CDP];
__device__ float g_kh [(size_t)CB*CH*CS*CDP];
__device__ float g_vh [(size_t)CB*CH*CS*CDP];
__device__ float g_attn[(size_t)CBS*CD];
__device__ float g_res[(size_t)CBS*CD];
__device__ float g_h1 [(size_t)CBS*CFF];   // QKV output, later FFN intermediate
__device__ float g_wqkv[(size_t)CD*CFF];   // packed [1080][3240] Wq|Wk|Wv (RN tf32)
__device__ float g_bqkv[CFF];
__device__ float g_wr [(size_t)11664000];  // RN-rounded Wo|W1|W3|W2
#define WR_WO 0
#define WR_W1 1166400
#define WR_W3 4665600
#define WR_W2 8164800

enum { EPI_NONE=0, EPI_SCALE=1, EPI_BIAS=2, EPI_BIAS_RES=3, EPI_SWIGLU=4 };

__device__ __forceinline__ float rn_tf32(float x)
{
    float r;
    asm("cvt.rna.tf32.f32 %0, %1;" : "=f"(r) : "f"(x));
    return r;
}

__device__ __forceinline__ void cp_async16(float* smem, const float* gmem, bool pred)
{
    unsigned saddr = (unsigned)__cvta_generic_to_shared(smem);
    int sz = pred ? 16 : 0;
    asm volatile("cp.async.cg.shared.global [%0], [%1], 16, %2;\n"
                 :: "r"(saddr), "l"(gmem), "r"(sz));
}
__device__ __forceinline__ void cp_commit() { asm volatile("cp.async.commit_group;\n"); }

// ---------------- TF32 tensor-core GEMM, 3-stage cp.async pipeline --------
#define ALD 24
#define BLD 136
#define CLD 24
#define STG_F (128*ALD)
#define SMEM_BYTES (3*STG_F*2*4)

template<int EPI>
__global__ __launch_bounds__(256, 2)
void gemm_tc(const float* __restrict__ A, int lda,
             const float* __restrict__ Bm, int ldb,
             float* __restrict__ C, int ldc,
             const float* __restrict__ bias,
             const float* __restrict__ aux, int ldx,
             int M, int N, int K)
{
    const int m0 = blockIdx.y * 128;
    const int n0 = blockIdx.x * 128;
    const int kEnd  = K;
    const int nIter = (kEnd + 15) >> 4;

    extern __shared__ __align__(16) float smem_dyn[];
    float* As = smem_dyn;
    float* Bs = smem_dyn + 3 * STG_F;

    const int tid = threadIdx.x;
    const int wid = tid >> 5;
    const int lane = tid & 31;
    const int warp_m = wid & 3;
    const int warp_n = wid >> 2;

    const int aRow = tid >> 1;
    const int aC0  = (tid & 1) * 8;
    const int bRowN = tid >> 4;
    const int bC0N  = (tid & 15) * 8;

    const bool aRowOk = (m0 + aRow) < M;
    const float* aBase = A + (long)(m0 + aRow) * lda + aC0;
    const float* bBaseN = Bm + (long)bRowN * ldb + n0 + bC0N;
    const bool bColOkN = (n0 + bC0N) < N;
    const bool bColOkN4 = (n0 + bC0N + 4) < N;

    wmma::fragment<wmma::accumulator, 16, 16, 8, float> acc[2][4];
    #pragma unroll
    for (int i = 0; i < 2; i++)
        #pragma unroll
        for (int j = 0; j < 4; j++) wmma::fill_fragment(acc[i][j], 0.f);

    auto issue = [&](int it, int buf) {
        const int k0 = it << 4;
        float* as = As + buf * STG_F;
        float* bs = Bs + buf * STG_F;
        cp_async16(&as[aRow * ALD + aC0],     aBase + k0,     aRowOk && (k0 + aC0     < kEnd));
        cp_async16(&as[aRow * ALD + aC0 + 4], aBase + k0 + 4, aRowOk && (k0 + aC0 + 4 < kEnd));
        const bool rOk = (k0 + bRowN) < kEnd;
        cp_async16(&bs[bRowN * BLD + bC0N],     bBaseN + (long)k0 * ldb,     rOk && bColOkN);
        cp_async16(&bs[bRowN * BLD + bC0N + 4], bBaseN + (long)k0 * ldb + 4, rOk && bColOkN4);
    };

    issue(0, 0);
    cp_commit();
    if (nIter > 1) { issue(1, 1); cp_commit(); }

    for (int it = 0; it < nIter; it++) {
        const int buf = it % 3;
        if (it + 1 < nIter) asm volatile("cp.async.wait_group 1;\n");
        else                asm volatile("cp.async.wait_group 0;\n");
        __syncthreads();
        if (it + 2 < nIter) { issue(it + 2, (it + 2) % 3); cp_commit(); }

        const float* as = As + buf * STG_F;
        const float* bs = Bs + buf * STG_F;
        #pragma unroll
        for (int kk = 0; kk < 16; kk += 8) {
            wmma::fragment<wmma::matrix_a, 16, 16, 8, wmma::precision::tf32, wmma::row_major> af[2];
            #pragma unroll
            for (int i = 0; i < 2; i++)
                wmma::load_matrix_sync(af[i], &as[(warp_m * 32 + i * 16) * ALD + kk], ALD);
            #pragma unroll
            for (int j = 0; j < 4; j++) {
                wmma::fragment<wmma::matrix_b, 16, 16, 8, wmma::precision::tf32, wmma::row_major> bf;
                wmma::load_matrix_sync(bf, &bs[kk * BLD + warp_n * 64 + j * 16], BLD);
                wmma::mma_sync(acc[0][j], af[0], bf, acc[0][j]);
                wmma::mma_sync(acc[1][j], af[1], bf, acc[1][j]);
            }
        }
        __syncthreads();
    }

    // epilogue
    float* stage = &As[wid * 16 * CLD];
    const int er  = lane >> 1;
    const int ec0 = (lane & 1) * 8;
    #pragma unroll
    for (int i = 0; i < 2; i++) {
        #pragma unroll
        for (int j = 0; j < 4; j++) {
            wmma::store_matrix_sync(stage, acc[i][j], CLD, wmma::mem_row_major);
            __syncwarp();
            const int gr = m0 + warp_m * 32 + i * 16 + er;
            const int gcb = n0 + warp_n * 64 + j * 16 + ec0;
            if (gr < M) {
                #pragma unroll
                for (int u = 0; u < 8; u++) {
                    const int gc = gcb + u;
                    if (gc >= N) break;
                    float v = stage[er * CLD + ec0 + u];
                    if (EPI == EPI_BIAS)     v += bias[gc];
                    if (EPI == EPI_BIAS_RES) v += bias[gc] + aux[(long)gr * ldx + gc];
                    if (EPI == EPI_SWIGLU) {
                        float h = aux[(long)gr * ldx + gc];
                        float sg = h / (1.f + __expf(-h));
                        v = rn_tf32(sg * (v + bias[gc]));    // feeds W2 GEMM
                    }
                    C[(long)gr * ldc + gc] = v;
                }
            }
            __syncwarp();
        }
    }
}

// ---------------- flash attention (fused QK^T + softmax + PV) --------------
// One CTA per (head, 64-row q tile). Streams 64-row K/V tiles. O in registers.
#define FQ 64
#define FN 64
#define QLD 100
#define SLD 100
#define FLASH_SMEM ((4*FQ*QLD + 3*FQ)*4)   // 103168 B

__global__ __launch_bounds__(256, 2)
void flash_k(const float* __restrict__ qh, const float* __restrict__ kh,
             const float* __restrict__ vh, float* __restrict__ attn, float iscale)
{
    const int zi = blockIdx.y;                       // b*CH + h
    const int iT = (int)gridDim.x - 1 - (int)blockIdx.x;  // heavy tiles first
    const int i0 = iT * FQ;
    const int tid = threadIdx.x;
    const int wid = tid >> 5;

    const float* Qp = qh + (long)zi * CS * CDP;
    const float* Kp = kh + (long)zi * CS * CDP;
    const float* Vp = vh + (long)zi * CS * CDP;

    extern __shared__ __align__(16) float sm[];
    float* Qs = sm;
    float* Ks = Qs + FQ * QLD;
    float* Vs = Ks + FQ * QLD;
    float* Ss = Vs + FQ * QLD;
    float* mrow = Ss + FQ * SLD;
    float* lrow = mrow + FQ;
    float* arow = lrow + FQ;

    // Q tile load
    for (int t = tid; t < FQ * 24; t += 256) {
        int r = t / 24, c4 = (t % 24) * 4;
        cp_async16(&Qs[r * QLD + c4], Qp + (long)(i0 + r) * CDP + c4, (i0 + r) < CS);
    }
    cp_commit();
    if (tid < FQ) { mrow[tid] = -1e30f; lrow[tid] = 0.f; }
    float Oreg[24];
    #pragma unroll
    for (int e = 0; e < 24; e++) Oreg[e] = 0.f;
    asm volatile("cp.async.wait_group 0;\n");
    __syncthreads();

    const int warp_m = wid & 3;     // 16 rows
    const int warp_n = wid >> 2;    // S: 32 cols ; PV: 48 cols
    const int r4 = tid >> 2, t4 = tid & 3;

    for (int j = 0; j <= iT; j++) {
        const int j0 = j * FN;
        // K then V (separate groups so S GEMM overlaps V load)
        for (int t = tid; t < FN * 24; t += 256) {
            int r = t / 24, c4 = (t % 24) * 4;
            cp_async16(&Ks[r * QLD + c4], Kp + (long)(j0 + r) * CDP + c4, (j0 + r) < CS);
        }
        cp_commit();
        for (int t = tid; t < FN * 24; t += 256) {
            int r = t / 24, c4 = (t % 24) * 4;
            cp_async16(&Vs[r * QLD + c4], Vp + (long)(j0 + r) * CDP + c4, (j0 + r) < CS);
        }
        cp_commit();
        asm volatile("cp.async.wait_group 1;\n");   // K ready, V in flight
        __syncthreads();

        // S = Q K^T  (warp: 16 x 32, 2 frags)
        {
            wmma::fragment<wmma::accumulator, 16, 16, 8, float> sacc[2];
            wmma::fill_fragment(sacc[0], 0.f);
            wmma::fill_fragment(sacc[1], 0.f);
            #pragma unroll
            for (int kk = 0; kk < CDP; kk += 8) {
                wmma::fragment<wmma::matrix_a, 16, 16, 8, wmma::precision::tf32, wmma::row_major> af;
                wmma::load_matrix_sync(af, &Qs[(warp_m * 16) * QLD + kk], QLD);
                #pragma unroll
                for (int f = 0; f < 2; f++) {
                    wmma::fragment<wmma::matrix_b, 16, 16, 8, wmma::precision::tf32, wmma::col_major> bf;
                    wmma::load_matrix_sync(bf, &Ks[(warp_n * 32 + f * 16) * QLD + kk], QLD);
                    wmma::mma_sync(sacc[f], af, bf, sacc[f]);
                }
            }
            #pragma unroll
            for (int f = 0; f < 2; f++)
                wmma::store_matrix_sync(&Ss[(warp_m * 16) * SLD + warp_n * 32 + f * 16],
                                        sacc[f], SLD, wmma::mem_row_major);
        }
        __syncthreads();

        // online softmax: 4 threads per row, skewed conflict-free cols
        {
            const int r = r4;
            const int ig = i0 + r;
            const bool diag = (j == iT);
            float sv[16];
            float mloc = -1e30f;
            #pragma unroll
            for (int ii = 0; ii < 16; ii++) {
                int c = t4 + 4 * ii;
                float s = Ss[r * SLD + c] * iscale;
                if (diag && (j0 + c) > ig) s = -1e30f;
                sv[ii] = s;
                mloc = fmaxf(mloc, s);
            }
            mloc = fmaxf(mloc, __shfl_xor_sync(0xffffffffu, mloc, 1));
            mloc = fmaxf(mloc, __shfl_xor_sync(0xffffffffu, mloc, 2));
            const float mprev = mrow[r];
            const float mnew = fmaxf(mprev, mloc);
            float sum = 0.f;
            #pragma unroll
            for (int ii = 0; ii < 16; ii++) {
                int c = t4 + 4 * ii;
                float p = rn_tf32(__expf(sv[ii] - mnew));
                Ss[r * SLD + c] = p;
                sum += p;
            }
            sum += __shfl_xor_sync(0xffffffffu, sum, 1);
            sum += __shfl_xor_sync(0xffffffffu, sum, 2);
            if (t4 == 0) {
                float alpha = __expf(mprev - mnew);
                arow[r] = alpha;
                lrow[r] = lrow[r] * alpha + sum;
                mrow[r] = mnew;
            }
        }
        asm volatile("cp.async.wait_group 0;\n");   // V ready
        __syncthreads();

        // PV (warp: 16 x 48, 3 frags), then write PV result back into Ss
        {
            wmma::fragment<wmma::accumulator, 16, 16, 8, float> pacc[3];
            #pragma unroll
            for (int f = 0; f < 3; f++) wmma::fill_fragment(pacc[f], 0.f);
            #pragma unroll
            for (int kk = 0; kk < FN; kk += 8) {
                wmma::fragment<wmma::matrix_a, 16, 16, 8, wmma::precision::tf32, wmma::row_major> af;
                wmma::load_matrix_sync(af, &Ss[(warp_m * 16) * SLD + kk], SLD);
                #pragma unroll
                for (int f = 0; f < 3; f++) {
                    wmma::fragment<wmma::matrix_b, 16, 16, 8, wmma::precision::tf32, wmma::row_major> bf;
                    wmma::load_matrix_sync(bf, &Vs[kk * QLD + warp_n * 48 + f * 16], QLD);
                    wmma::mma_sync(pacc[f], af, bf, pacc[f]);
                }
            }
            __syncthreads();   // all P reads done before overwriting Ss
            #pragma unroll
            for (int f = 0; f < 3; f++)
                wmma::store_matrix_sync(&Ss[(warp_m * 16) * SLD + warp_n * 48 + f * 16],
                                        pacc[f], SLD, wmma::mem_row_major);
        }
        __syncthreads();

        // merge into O registers
        #pragma unroll
        for (int e = 0; e < 24; e++) {
            int idx = tid + 256 * e;
            int r = idx / 96, c = idx - r * 96;
            Oreg[e] = Oreg[e] * arow[r] + Ss[r * SLD + c];
        }
        __syncthreads();
    }

    // write out (interleaved [B,S,D]); RN-round for the O-projection GEMM
    const int b = zi / CH, h = zi - b * CH;
    #pragma unroll
    for (int e = 0; e < 24; e++) {
        int idx = tid + 256 * e;
        int r = idx / 96, c = idx - r * 96;
        int ig = i0 + r;
        if (ig < CS && c < CDK)
            attn[((long)b * CS + ig) * CD + h * CDK + c] = rn_tf32(Oreg[e] / lrow[r]);
    }
}

// ---------------- RN-round copy (float4) ----------------
__global__ __launch_bounds__(256)
void round4_k(const float* __restrict__ s, float* __restrict__ d, int n4)
{
    int i = blockIdx.x * 256 + threadIdx.x;
    if (i < n4) {
        float4 v = reinterpret_cast<const float4*>(s)[i];
        v.x = rn_tf32(v.x); v.y = rn_tf32(v.y);
        v.z = rn_tf32(v.z); v.w = rn_tf32(v.w);
        reinterpret_cast<float4*>(d)[i] = v;
    }
}

// ---------------- pack Wq|Wk|Wv (RN-rounded) -> [1080][3240] ----------
__global__ __launch_bounds__(256)
void pack_qkv_k(const float* __restrict__ Wq, const float* __restrict__ Wk,
                const float* __restrict__ Wv,
                const float* __restrict__ bq, const float* __restrict__ bk,
                const float* __restrict__ bv,
                float* __restrict__ W, float* __restrict__ b)
{
    const int NW4 = CD * (CD / 4);
    long idx = (long)blockIdx.x * 256 + threadIdx.x;
    if (idx < NW4) {
        int r = (int)(idx / (CD / 4));
        int c = (int)(idx % (CD / 4)) * 4;
        float4 vq = *reinterpret_cast<const float4*>(Wq + (long)r * CD + c);
        float4 vk = *reinterpret_cast<const float4*>(Wk + (long)r * CD + c);
        float4 vv = *reinterpret_cast<const float4*>(Wv + (long)r * CD + c);
        vq.x=rn_tf32(vq.x); vq.y=rn_tf32(vq.y); vq.z=rn_tf32(vq.z); vq.w=rn_tf32(vq.w);
        vk.x=rn_tf32(vk.x); vk.y=rn_tf32(vk.y); vk.z=rn_tf32(vk.z); vk.w=rn_tf32(vk.w);
        vv.x=rn_tf32(vv.x); vv.y=rn_tf32(vv.y); vv.z=rn_tf32(vv.z); vv.w=rn_tf32(vv.w);
        *reinterpret_cast<float4*>(W + (long)r * CFF + c)          = vq;
        *reinterpret_cast<float4*>(W + (long)r * CFF + CD + c)     = vk;
        *reinterpret_cast<float4*>(W + (long)r * CFF + 2 * CD + c) = vv;
    } else if (idx < NW4 + CD / 4) {
        int c = (int)(idx - NW4) * 4;
        *reinterpret_cast<float4*>(b + c)          = *reinterpret_cast<const float4*>(bq + c);
        *reinterpret_cast<float4*>(b + CD + c)     = *reinterpret_cast<const float4*>(bk + c);
        *reinterpret_cast<float4*>(b + 2 * CD + c) = *reinterpret_cast<const float4*>(bv + c);
    }
}

// ---------------- layernorm (RN-rounded output) ----------------
__global__ __launch_bounds__(256)
void ln_k(const float* __restrict__ x, const float* __restrict__ g,
          const float* __restrict__ b, float* __restrict__ y)
{
    const long row = blockIdx.x;
    const float* xr = x + row * CD;
    float* yr = y + row * CD;

    float s = 0.f, s2 = 0.f;
    for (int i = threadIdx.x; i < CD; i += 256) {
        float v = xr[i]; s += v; s2 += v * v;
    }
    __shared__ float rs[8], rs2[8];
    __shared__ float bm, br;
    #pragma unroll
    for (int o = 16; o; o >>= 1) {
        s  += __shfl_xor_sync(0xffffffffu, s,  o);
        s2 += __shfl_xor_sync(0xffffffffu, s2, o);
    }
    if ((threadIdx.x & 31) == 0) { rs[threadIdx.x >> 5] = s; rs2[threadIdx.x >> 5] = s2; }
    __syncthreads();
    if (threadIdx.x < 8) {
        float a = rs[threadIdx.x], a2 = rs2[threadIdx.x];
        #pragma unroll
        for (int o = 4; o; o >>= 1) {
            a  += __shfl_xor_sync(0xffu, a,  o);
            a2 += __shfl_xor_sync(0xffu, a2, o);
        }
        if (threadIdx.x == 0) {
            float mean = a / CD;
            float var  = a2 / CD - mean * mean;
            bm = mean;
            br = rsqrtf(var + 1e-5f);
        }
    }
    __syncthreads();
    const float mean = bm, rstd = br;
    for (int i = threadIdx.x; i < CD; i += 256)
        yr[i] = rn_tf32((xr[i] - mean) * rstd * g[i] + b[i]);
}

// -------- RoPE + repack from fused QKV [row][3240] to [B*H, S, 96], RN out --
__global__ __launch_bounds__(256)
void rope_repack_k(const float* __restrict__ qkv,
                   const float* __restrict__ ct, const float* __restrict__ st,
                   float* __restrict__ qh, float* __restrict__ kh,
                   float* __restrict__ vh)
{
    const long total = (long)CB * CH * CS * 48;
    long idx = (long)blockIdx.x * 256 + threadIdx.x;
    if (idx >= total) return;
    const int d = (int)(idx % 48);  idx /= 48;
    const int s = (int)(idx % CS);  idx /= CS;
    const int h = (int)(idx % CH);
    const int b = (int)(idx / CH);

    const long src = ((long)b * CS + s) * CFF + h * CDK;
    const long dst = (((long)b * CH + h) * CS + s) * CDP;

    if (d < 45) {
        const float c1 = ct[s * CDK + d],      s1 = st[s * CDK + d];
        const float c2 = ct[s * CDK + d + 45], s2 = st[s * CDK + d + 45];
        float q1 = qkv[src + d],          q2 = qkv[src + d + 45];
        qh[dst + d]      = rn_tf32(q1 * c1 - q2 * s1);
        qh[dst + d + 45] = rn_tf32(q2 * c2 + q1 * s2);
        float k1 = qkv[src + CD + d],     k2 = qkv[src + CD + d + 45];
        kh[dst + d]      = rn_tf32(k1 * c1 - k2 * s1);
        kh[dst + d + 45] = rn_tf32(k2 * c2 + k1 * s2);
        vh[dst + d]      = rn_tf32(qkv[src + 2 * CD + d]);
        vh[dst + d + 45] = rn_tf32(qkv[src + 2 * CD + d + 45]);
    } else {
        const int p = 90 + 2 * (d - 45);
        qh[dst + p] = 0.f; qh[dst + p + 1] = 0.f;
        kh[dst + p] = 0.f; kh[dst + p + 1] = 0.f;
        vh[dst + p] = 0.f; vh[dst + p + 1] = 0.f;
    }
}

// ---------------- host launch ----------------
extern "C" void kernel_launch(void* const* d_in, const int* in_sizes, int n_in,
                              void* d_out, int out_size)
{
    const float* x    = (const float*)d_in[0];
    const float* Wq   = (const float*)d_in[2];
    const float* bq   = (const float*)d_in[3];
    const float* Wk   = (const float*)d_in[4];
    const float* bk   = (const float*)d_in[5];
    const float* Wv   = (const float*)d_in[6];
    const float* bv   = (const float*)d_in[7];
    const float* Wo   = (const float*)d_in[8];
    const float* bo   = (const float*)d_in[9];
    const float* W1   = (const float*)d_in[10];
    const float* b1   = (const float*)d_in[11];
    const float* W2   = (const float*)d_in[12];
    const float* b2   = (const float*)d_in[13];
    const float* W3   = (const float*)d_in[14];
    const float* b3   = (const float*)d_in[15];
    const float* ln1g = (const float*)d_in[16];
    const float* ln1b = (const float*)d_in[17];
    const float* ln2g = (const float*)d_in[18];
    const float* ln2b = (const float*)d_in[19];
    const float* rc   = (const float*)d_in[20];
    const float* rs   = (const float*)d_in[21];
    float* out = (float*)d_out;

    float *x2, *qh, *kh, *vh, *attn, *res, *h1, *wqkv, *bqkv, *wr;
    cudaGetSymbolAddress((void**)&x2,   g_x2);
    cudaGetSymbolAddress((void**)&qh,   g_qh);
    cudaGetSymbolAddress((void**)&kh,   g_kh);
    cudaGetSymbolAddress((void**)&vh,   g_vh);
    cudaGetSymbolAddress((void**)&attn, g_attn);
    cudaGetSymbolAddress((void**)&res,  g_res);
    cudaGetSymbolAddress((void**)&h1,   g_h1);
    cudaGetSymbolAddress((void**)&wqkv, g_wqkv);
    cudaGetSymbolAddress((void**)&bqkv, g_bqkv);
    cudaGetSymbolAddress((void**)&wr,   g_wr);

    cudaFuncSetAttribute(gemm_tc<EPI_BIAS>,     cudaFuncAttributeMaxDynamicSharedMemorySize, SMEM_BYTES);
    cudaFuncSetAttribute(gemm_tc<EPI_BIAS_RES>, cudaFuncAttributeMaxDynamicSharedMemorySize, SMEM_BYTES);
    cudaFuncSetAttribute(gemm_tc<EPI_SWIGLU>,   cudaFuncAttributeMaxDynamicSharedMemorySize, SMEM_BYTES);
    cudaFuncSetAttribute(flash_k,               cudaFuncAttributeMaxDynamicSharedMemorySize, FLASH_SMEM);

    const float iscale = 1.f / sqrtf((float)CDK);

    // 0) RN-round weights + pack QKV
    round4_k<<<(291600 + 255) / 256, 256>>>(Wo, wr + WR_WO, 291600);
    round4_k<<<(874800 + 255) / 256, 256>>>(W1, wr + WR_W1, 874800);
    round4_k<<<(874800 + 255) / 256, 256>>>(W3, wr + WR_W3, 874800);
    round4_k<<<(874800 + 255) / 256, 256>>>(W2, wr + WR_W2, 874800);
    {
        int total = CD * (CD / 4) + CD / 4;
        pack_qkv_k<<<(total + 255) / 256, 256>>>(Wq, Wk, Wv, bq, bk, bv, wqkv, bqkv);
    }

    // 1) LN1 (RN output)
    ln_k<<<CBS, 256>>>(x, ln1g, ln1b, x2);

    // 2) fused QKV projection
    dim3 gQKV((CFF + 127) / 128, (CBS + 127) / 128, 1);
    gemm_tc<EPI_BIAS><<<gQKV, 256, SMEM_BYTES>>>(
        x2, CD, wqkv, CFF, h1, CFF, bqkv, nullptr, 0, CBS, CFF, CD);

    // 3) RoPE + repack (RN output)
    {
        long total = (long)CB * CH * CS * 48;
        rope_repack_k<<<(unsigned)((total + 255) / 256), 256>>>(h1, rc, rs, qh, kh, vh);
    }

    // 4) flash attention (fused scores + softmax + PV)
    {
        dim3 g((CS + FQ - 1) / FQ, CB * CH);
        flash_k<<<g, 256, FLASH_SMEM>>>(qh, kh, vh, attn, iscale);
    }

    // 5) O-projection + bias + residual(x)
    dim3 gD((CD + 127) / 128, (CBS + 127) / 128, 1);
    gemm_tc<EPI_BIAS_RES><<<gD, 256, SMEM_BYTES>>>(
        attn, CD, wr + WR_WO, CD, res, CD, bo, x, CD, CBS, CD, CD);

    // 6) LN2
    ln_k<<<CBS, 256>>>(res, ln2g, ln2b, x2);

    // 7) h1 = x2@W1 + b1
    dim3 gF((CFF + 127) / 128, (CBS + 127) / 128, 1);
    gemm_tc<EPI_BIAS><<<gF, 256, SMEM_BYTES>>>(
        x2, CD, wr + WR_W1, CFF, h1, CFF, b1, nullptr, 0, CBS, CFF, CD);

    // 8) h1 = silu(h1) * (x2@W3 + b3)   (RN output)
    gemm_tc<EPI_SWIGLU><<<gF, 256, SMEM_BYTES>>>(
        x2, CD, wr + WR_W3, CFF, h1, CFF, b3, h1, CFF, CBS, CFF, CD);

    // 9) out = res + h1@W2 + b2
    gemm_tc<EPI_BIAS_RES><<<gD, 256, SMEM_BYTES>>>(
        h1, CFF, wr + WR_W2, CD, out, CD, b2, res, CD, CBS, CD, CFF);
}